// round 7
// baseline (speedup 1.0000x reference)
#include <cuda_runtime.h>
#include <cuda_bf16.h>
#include <cstdint>

// ---------------- problem constants ----------------
#define N_NODES 10000
#define M_PAD   10112            // 79 * 128
#define N_EDGES 100000
#define EE      110000           // edges + self loops
#define G_IN    2000
#define K1_PAD  2048
#define H       20
#define C       128
#define HC      2560             // H * C
#define NEG_SLOPE 0.2f

// ---------------- scratch (device globals; no allocations) ----------------
__device__ float g_h[(size_t)N_NODES * HC];
__device__ float g_o[(size_t)N_NODES * HC];
__device__ float g_asrc[N_NODES * H];
__device__ float g_adst[N_NODES * H];
__device__ float g_alpha[(size_t)EE * H];
__device__ int   g_rowptr[N_NODES + 1];
__device__ int   g_deg[N_NODES];
__device__ int   g_fill[N_NODES];
__device__ int   g_csrc[EE];
__device__ int   g_is64;
__device__ int   g_esrc[N_EDGES];
__device__ int   g_edst[N_EDGES];
// int8 two-digit splits: A [m][kpad], W^T [n][kpad]
__device__ int8_t g_a1[(size_t)M_PAD * HC];
__device__ int8_t g_a2[(size_t)M_PAD * HC];
__device__ int8_t g_b1[(size_t)HC * HC];
__device__ int8_t g_b2[(size_t)HC * HC];
__device__ float  g_sa[N_NODES];       // s_a * 2^-14  (includes the 128 factor fold? no: s/2^14 per derivation below)
__device__ int    g_sbbits[2][HC];     // per-n |W| max bits (atomicMax; deterministic)
__device__ float  g_sbf[2][HC];        // s_b * 2^-14

// ---------------- helpers ----------------
__device__ __forceinline__ uint32_t smem_u32(const void* p) {
    uint32_t a;
    asm("{ .reg .u64 t; cvta.to.shared.u64 t, %1; cvt.u32.u64 %0, t; }" : "=r"(a) : "l"(p));
    return a;
}
#define SWZ(off) ((off) ^ (((off) >> 3) & 0x70))

__device__ __forceinline__ void cp16(uint32_t dst, const void* src) {
    asm volatile("cp.async.cg.shared.global [%0], [%1], 16;" :: "r"(dst), "l"(src) : "memory");
}
__device__ __forceinline__ void cp_commit() {
    asm volatile("cp.async.commit_group;" ::: "memory");
}
template <int X> __device__ __forceinline__ void cp_wait() {
    asm volatile("cp.async.wait_group %0;" :: "n"(X) : "memory");
}
#define LDSM4(r0, r1, r2, r3, addr) \
    asm volatile("ldmatrix.sync.aligned.m8n8.x4.shared.b16 {%0,%1,%2,%3}, [%4];" \
        : "=r"(r0), "=r"(r1), "=r"(r2), "=r"(r3) : "r"(addr))
#define IMMA(c, a0, a1_, a2_, a3_, b0, b1_) \
    asm volatile("mma.sync.aligned.m16n8k32.row.col.s32.s8.s8.s32 " \
        "{%0,%1,%2,%3}, {%4,%5,%6,%7}, {%8,%9}, {%0,%1,%2,%3};" \
        : "+r"((c)[0]), "+r"((c)[1]), "+r"((c)[2]), "+r"((c)[3]) \
        : "r"(a0), "r"(a1_), "r"(a2_), "r"(a3_), "r"(b0), "r"(b1_))

// quantize one float: v = rint(x*inv) in [-16384,16384]; v = 128*a1 + a2
__device__ __forceinline__ void quant2(float x, float inv, int& a1, int& a2) {
    int v = __float2int_rn(x * inv);
    a1 = (v + 64) >> 7;
    if (a1 > 127) a1 = 127;
    a2 = v - (a1 << 7);
    if (a2 > 127) a2 = 127;
    if (a2 < -128) a2 = -128;
}

// ---------------- edge dtype detection + normalization ----------------
__global__ void k_detect(const int* __restrict__ ei32) {
    __shared__ int any;
    if (threadIdx.x == 0) any = 0;
    __syncthreads();
    if (ei32[2 * threadIdx.x + 1] != 0) atomicOr(&any, 1);
    __syncthreads();
    if (threadIdx.x == 0) g_is64 = (any == 0) ? 1 : 0;
}
__global__ void k_norm(const int* __restrict__ ei32) {
    int e = blockIdx.x * blockDim.x + threadIdx.x;
    if (e >= N_EDGES) return;
    if (g_is64) { g_esrc[e] = ei32[2 * e]; g_edst[e] = ei32[2 * N_EDGES + 2 * e]; }
    else        { g_esrc[e] = ei32[e];     g_edst[e] = ei32[N_EDGES + e]; }
}

// ---------------- CSR build ----------------
__global__ void k_zero_deg() {
    int i = blockIdx.x * blockDim.x + threadIdx.x;
    if (i < N_NODES) g_deg[i] = 0;
}
__global__ void k_count() {
    int e = blockIdx.x * blockDim.x + threadIdx.x;
    if (e >= EE) return;
    int dst = (e < N_EDGES) ? g_edst[e] : (e - N_EDGES);
    atomicAdd(&g_deg[dst], 1);
}
__global__ void k_scan() {
    __shared__ int part[1024];
    int t = threadIdx.x;
    const int CH = (N_NODES + 1023) / 1024;
    int base = t * CH, s = 0;
    for (int i = 0; i < CH; i++) { int idx = base + i; if (idx < N_NODES) s += g_deg[idx]; }
    part[t] = s;
    __syncthreads();
    for (int o = 1; o < 1024; o <<= 1) {
        int v = (t >= o) ? part[t - o] : 0;
        __syncthreads(); part[t] += v; __syncthreads();
    }
    int run = (t > 0) ? part[t - 1] : 0;
    for (int i = 0; i < CH; i++) {
        int idx = base + i;
        if (idx < N_NODES) { g_rowptr[idx] = run; g_fill[idx] = run; run += g_deg[idx]; }
    }
    if (t == 1023) g_rowptr[N_NODES] = part[1023];
}
__global__ void k_scatter() {
    int e = blockIdx.x * blockDim.x + threadIdx.x;
    if (e >= EE) return;
    int src, dst;
    if (e < N_EDGES) { src = g_esrc[e]; dst = g_edst[e]; }
    else             { src = e - N_EDGES; dst = src; }
    int pos = atomicAdd(&g_fill[dst], 1);
    g_csrc[pos] = src;
}

// ---------------- A quantization: per-row amax + two-digit int8 split ----------------
template <bool LAYER2>
__global__ void k_aq(const float* __restrict__ Aext, int K, int KPAD) {
    const float* __restrict__ A = LAYER2 ? (const float*)g_o : Aext;
    __shared__ float red[256];
    __shared__ float sh_inv;
    int row = blockIdx.x;
    const float* ap = A + (size_t)row * K;
    float m = 0.f;
    for (int k = threadIdx.x; k < K; k += 256) m = fmaxf(m, fabsf(ap[k]));
    red[threadIdx.x] = m;
    __syncthreads();
    for (int o = 128; o; o >>= 1) {
        if (threadIdx.x < o) red[threadIdx.x] = fmaxf(red[threadIdx.x], red[threadIdx.x + o]);
        __syncthreads();
    }
    if (threadIdx.x == 0) {
        float mm = red[0];
        if (mm > 0.f) {
            int E; frexpf(mm, &E);            // mm = f * 2^E, f in [0.5,1)
            sh_inv = ldexpf(1.f, 14 - E);     // x*inv in [-16384,16384]
            g_sa[row] = ldexpf(1.f, E - 14);  // s * 2^-15 where s = 2^(E+1)
        } else { sh_inv = 0.f; g_sa[row] = 0.f; }
    }
    __syncthreads();
    float inv = sh_inv;
    for (int k4 = threadIdx.x * 4; k4 < KPAD; k4 += 1024) {
        uint32_t w1 = 0, w2 = 0;
        if (k4 < K) {   // K is a multiple of 4
            #pragma unroll
            for (int j = 0; j < 4; j++) {
                int a1, a2; quant2(ap[k4 + j], inv, a1, a2);
                w1 |= (uint32_t)(a1 & 0xff) << (8 * j);
                w2 |= (uint32_t)(a2 & 0xff) << (8 * j);
            }
        }
        size_t o = (size_t)row * KPAD + k4;
        *(uint32_t*)(g_a1 + o) = w1;
        *(uint32_t*)(g_a2 + o) = w2;
    }
}

// ---------------- W per-column amax (atomicMax is order-independent => deterministic) ----------------
__global__ void k_wmax(const float* __restrict__ W, int K, int layer) {
    int n  = blockIdx.x * 256 + threadIdx.x;
    int k0 = blockIdx.y * 32;
    float m = 0.f;
    for (int i = 0; i < 32; i++) {
        int k = k0 + i;
        if (k < K) m = fmaxf(m, fabsf(W[(size_t)k * HC + n]));
    }
    atomicMax(&g_sbbits[layer][n], __float_as_int(m));
}

// ---------------- W transpose + int8 split: g_b1/g_b2[n][kpad] ----------------
__global__ void k_wsplitq(const float* __restrict__ W, int K, int KPAD, int layer) {
    __shared__ float tile[32][33];
    int n0 = blockIdx.y * 32, k0 = blockIdx.x * 32;
    int tx = threadIdx.x, ty = threadIdx.y;     // (32, 8)
    #pragma unroll
    for (int s = 0; s < 32; s += 8) {
        int k = k0 + ty + s;
        tile[ty + s][tx] = (k < K) ? W[(size_t)k * HC + n0 + tx] : 0.f;
    }
    __syncthreads();
    #pragma unroll
    for (int s = 0; s < 32; s += 8) {
        int n = n0 + ty + s;
        int k = k0 + tx;
        float mm = __int_as_float(g_sbbits[layer][n]);
        float inv = 0.f, sv = 0.f;
        if (mm > 0.f) {
            int E; frexpf(mm, &E);
            inv = ldexpf(1.f, 14 - E);
            sv  = ldexpf(1.f, E - 14);
        }
        if (k0 == 0 && tx == 0) g_sbf[layer][n] = sv;
        int a1, a2; quant2(tile[tx][ty + s], inv, a1, a2);
        g_b1[(size_t)n * KPAD + k] = (int8_t)a1;
        g_b2[(size_t)n * KPAD + k] = (int8_t)a2;
    }
}

// ---------------- int8 two-digit IMMA GEMM: g_h[M][HC] = A @ W ----------------
// CTA 128x128, TBK=128 int8, 3-stage cp.async pipeline, warp tile 64x32.
#define ISTG    65536
#define IOFF_A2 16384
#define IOFF_B1 32768
#define IOFF_B2 49152
#define IGSMEM  (3 * ISTG)      // 192 KB

__global__ __launch_bounds__(256, 1)
void k_igemm(int kpad, int layer)
{
    extern __shared__ char smem[];
    uint32_t sb_ = smem_u32(smem);
    int tid  = threadIdx.x;
    int lane = tid & 31;
    int wid  = tid >> 5;
    int wr   = wid >> 2;            // 0..1 (64-row slabs)
    int wc   = wid & 3;             // 0..3 (32-col slabs)
    int row0 = blockIdx.y * 128;
    int col0 = blockIdx.x * 128;
    int nkb  = kpad >> 7;

    int acc1[4][4][4], accX[4][4][4];
    #pragma unroll
    for (int i = 0; i < 4; i++)
        #pragma unroll
        for (int j = 0; j < 4; j++)
            #pragma unroll
            for (int q = 0; q < 4; q++) { acc1[i][j][q] = 0; accX[i][j][q] = 0; }

    // ---- stage issue: 16 cp.async per thread (64 KB total) ----
    auto issue = [&](int kb) {
        int kt = kb << 7;
        uint32_t st = sb_ + (kb % 3) * ISTG;
        #pragma unroll
        for (int i = 0; i < 4; i++) {
            int idx = i * 256 + tid;          // 0..1023
            int r = idx >> 3, c = idx & 7;
            uint32_t off = SWZ((uint32_t)(r * 128 + c * 16));
            size_t ga = (size_t)(row0 + r) * kpad + kt + c * 16;
            size_t gb = (size_t)(col0 + r) * kpad + kt + c * 16;
            cp16(st + off,           g_a1 + ga);
            cp16(st + IOFF_A2 + off, g_a2 + ga);
            cp16(st + IOFF_B1 + off, g_b1 + gb);
            cp16(st + IOFF_B2 + off, g_b2 + gb);
        }
    };

    issue(0); cp_commit();
    if (nkb > 1) issue(1);
    cp_commit();

    for (int kb = 0; kb < nkb; kb++) {
        cp_wait<1>();
        __syncthreads();
        if (kb + 2 < nkb) issue(kb + 2);
        cp_commit();

        uint32_t tb = sb_ + (kb % 3) * ISTG;
        #pragma unroll
        for (int s = 0; s < 4; s++) {         // 4 x k32 per 128-byte stage
            uint32_t a1f[4][4], a2f[4][4], b1f[4][2], b2f[4][2];
            int arow = wr * 64 + (lane & 15);
            uint32_t acol = (uint32_t)(s * 32 + (lane >> 4) * 16);
            #pragma unroll
            for (int mt = 0; mt < 4; mt++) {
                uint32_t off = SWZ((uint32_t)((arow + mt * 16) * 128) + acol);
                LDSM4(a1f[mt][0], a1f[mt][1], a1f[mt][2], a1f[mt][3], tb + off);
                LDSM4(a2f[mt][0], a2f[mt][1], a2f[mt][2], a2f[mt][3], tb + IOFF_A2 + off);
            }
            int mi = lane >> 3;
            int brow = wc * 32 + ((mi >> 1) << 3) + (lane & 7);
            uint32_t bcol = (uint32_t)(s * 32 + (mi & 1) * 16);
            #pragma unroll
            for (int g = 0; g < 2; g++) {
                uint32_t off = SWZ((uint32_t)((brow + g * 16) * 128) + bcol);
                LDSM4(b1f[g * 2][0], b1f[g * 2][1], b1f[g * 2 + 1][0], b1f[g * 2 + 1][1],
                      tb + IOFF_B1 + off);
                LDSM4(b2f[g * 2][0], b2f[g * 2][1], b2f[g * 2 + 1][0], b2f[g * 2 + 1][1],
                      tb + IOFF_B2 + off);
            }
            #pragma unroll
            for (int mt = 0; mt < 4; mt++)
                #pragma unroll
                for (int nt = 0; nt < 4; nt++) {
                    IMMA(acc1[mt][nt], a1f[mt][0], a1f[mt][1], a1f[mt][2], a1f[mt][3],
                         b1f[nt][0], b1f[nt][1]);
                    IMMA(accX[mt][nt], a1f[mt][0], a1f[mt][1], a1f[mt][2], a1f[mt][3],
                         b2f[nt][0], b2f[nt][1]);
                    IMMA(accX[mt][nt], a2f[mt][0], a2f[mt][1], a2f[mt][2], a2f[mt][3],
                         b1f[nt][0], b1f[nt][1]);
                }
        }
    }

    // ---- epilogue: y = sa[m]*sb[n]*(16384*C11 + 128*Ccross) ----
    #pragma unroll
    for (int mt = 0; mt < 4; mt++) {
        int gr = row0 + wr * 64 + mt * 16 + (lane >> 2);
        float sA0 = (gr     < N_NODES) ? g_sa[gr]     : 0.f;
        float sA1 = (gr + 8 < N_NODES) ? g_sa[gr + 8] : 0.f;
        #pragma unroll
        for (int nt = 0; nt < 4; nt++) {
            int gc = col0 + wc * 32 + nt * 8 + (lane & 3) * 2;
            float sB0 = g_sbf[layer][gc];
            float sB1 = g_sbf[layer][gc + 1];
            float v0 = 16384.f * (float)acc1[mt][nt][0] + 128.f * (float)accX[mt][nt][0];
            float v1 = 16384.f * (float)acc1[mt][nt][1] + 128.f * (float)accX[mt][nt][1];
            float v2 = 16384.f * (float)acc1[mt][nt][2] + 128.f * (float)accX[mt][nt][2];
            float v3 = 16384.f * (float)acc1[mt][nt][3] + 128.f * (float)accX[mt][nt][3];
            if (gr < N_NODES)
                *(float2*)&g_h[(size_t)gr * HC + gc] = make_float2(sA0 * sB0 * v0, sA0 * sB1 * v1);
            if (gr + 8 < N_NODES)
                *(float2*)&g_h[(size_t)(gr + 8) * HC + gc] = make_float2(sA1 * sB0 * v2, sA1 * sB1 * v3);
        }
    }
}

// ---------------- attention scores ----------------
__global__ void k_att(const float* __restrict__ wsrc,
                      const float* __restrict__ wdst)
{
    int gw   = (blockIdx.x * blockDim.x + threadIdx.x) >> 5;
    int lane = threadIdx.x & 31;
    if (gw >= N_NODES * H) return;
    int n  = gw / H;
    int hh = gw - n * H;
    const float* hp = g_h + (size_t)n * HC + hh * C;
    const float* ws = wsrc + hh * C;
    const float* wd = wdst + hh * C;
    float s1 = 0.f, s2 = 0.f;
    #pragma unroll
    for (int i = 0; i < 4; i++) {
        float v = hp[lane + i * 32];
        s1 += v * __ldg(&ws[lane + i * 32]);
        s2 += v * __ldg(&wd[lane + i * 32]);
    }
    #pragma unroll
    for (int o = 16; o; o >>= 1) {
        s1 += __shfl_down_sync(0xffffffffu, s1, o);
        s2 += __shfl_down_sync(0xffffffffu, s2, o);
    }
    if (lane == 0) { g_asrc[gw] = s1; g_adst[gw] = s2; }
}

// ---------------- per-(dst,head) softmax ----------------
__global__ void k_softmax() {
    int idx = blockIdx.x * blockDim.x + threadIdx.x;
    if (idx >= N_NODES * H) return;
    int dst = idx / H;
    int hh  = idx - dst * H;
    float ad = g_adst[dst * H + hh];
    int p0 = g_rowptr[dst], p1 = g_rowptr[dst + 1];
    float m = -1e30f;
    for (int p = p0; p < p1; p++) {
        int s = g_csrc[p];
        float ev = g_asrc[s * H + hh] + ad;
        ev = (ev > 0.f) ? ev : NEG_SLOPE * ev;
        g_alpha[(size_t)p * H + hh] = ev;
        m = fmaxf(m, ev);
    }
    float sum = 0.f;
    for (int p = p0; p < p1; p++) {
        float ex = __expf(g_alpha[(size_t)p * H + hh] - m);
        g_alpha[(size_t)p * H + hh] = ex;
        sum += ex;
    }
    float inv = 1.f / sum;
    for (int p = p0; p < p1; p++) g_alpha[(size_t)p * H + hh] *= inv;
}

// ---------------- layer-1 aggregation ----------------
__global__ __launch_bounds__(256)
void k_agg1(const float* __restrict__ b1)
{
    __shared__ float sal[H];
    int dst = blockIdx.x;
    int t   = threadIdx.x;
    int p0 = g_rowptr[dst], p1 = g_rowptr[dst + 1];
    float acc[10];
    #pragma unroll
    for (int j = 0; j < 10; j++) acc[j] = 0.f;

    for (int p = p0; p < p1; p++) {
        if (t < H) sal[t] = g_alpha[(size_t)p * H + t];
        __syncthreads();
        const float* hs = g_h + (size_t)g_csrc[p] * HC;
        #pragma unroll
        for (int j = 0; j < 10; j++) {
            int c = t + j * 256;
            acc[j] += sal[c >> 7] * hs[c];
        }
        __syncthreads();
    }
    float* op = g_o + (size_t)dst * HC;
    #pragma unroll
    for (int j = 0; j < 10; j++) {
        int c = t + j * 256;
        float v = acc[j] + b1[c];
        op[c] = (v > 0.f) ? v : 0.f;
    }
}

// ---------------- layer-2 aggregation ----------------
__global__ __launch_bounds__(128)
void k_agg2(const float* __restrict__ b2, float* __restrict__ out)
{
    __shared__ float sal[H];
    int dst = blockIdx.x;
    int t   = threadIdx.x;
    int p0 = g_rowptr[dst], p1 = g_rowptr[dst + 1];
    float acc = 0.f;
    for (int p = p0; p < p1; p++) {
        if (t < H) sal[t] = g_alpha[(size_t)p * H + t];
        __syncthreads();
        const float* hs = g_h + (size_t)g_csrc[p] * HC;
        #pragma unroll
        for (int hh = 0; hh < H; hh++) acc += sal[hh] * hs[hh * C + t];
        __syncthreads();
    }
    float v = acc * (1.f / (float)H) + b2[t];
    out[dst * C + t] = (v > 0.f) ? v : 0.f;
}

// ---------------- launch ----------------
extern "C" void kernel_launch(void* const* d_in, const int* in_sizes, int n_in,
                              void* d_out, int out_size)
{
    const float* x   = (const float*)d_in[0];
    const int*   ei  = (const int*)d_in[1];
    const float* W1  = (const float*)d_in[2];
    const float* as1 = (const float*)d_in[3];
    const float* ad1 = (const float*)d_in[4];
    const float* b1  = (const float*)d_in[5];
    const float* W2  = (const float*)d_in[6];
    const float* as2 = (const float*)d_in[7];
    const float* ad2 = (const float*)d_in[8];
    const float* b2  = (const float*)d_in[9];
    float* out = (float*)d_out;

    cudaFuncSetAttribute(k_igemm, cudaFuncAttributeMaxDynamicSharedMemorySize, IGSMEM);

    dim3 gg(HC / 128, M_PAD / 128);                 // (20, 79)
    int att_blocks = (N_NODES * H * 32 + 255) / 256;
    int sm_blocks  = (N_NODES * H + 255) / 256;
    dim3 wsb(32, 8);

    // ----- layer 1 (k_igemm at launch #4 so ncu's fixed capture hits it) -----
    k_aq<false><<<N_NODES, 256>>>(x, G_IN, K1_PAD);                       // 1
    k_wmax<<<dim3(HC / 256, (G_IN + 31) / 32), 256>>>(W1, G_IN, 0);       // 2
    k_wsplitq<<<dim3(K1_PAD / 32, HC / 32), wsb>>>(W1, G_IN, K1_PAD, 0);  // 3
    k_igemm<<<gg, 256, IGSMEM>>>(K1_PAD, 0);                              // 4
    // edge normalization + CSR build
    k_detect<<<1, 256>>>(ei);
    k_norm  <<<(N_EDGES + 255) / 256, 256>>>(ei);
    k_zero_deg<<<(N_NODES + 255) / 256, 256>>>();
    k_count  <<<(EE + 255) / 256, 256>>>();
    k_scan   <<<1, 1024>>>();
    k_scatter<<<(EE + 255) / 256, 256>>>();
    // layer-1 edge phase
    k_att<<<att_blocks, 256>>>(as1, ad1);
    k_softmax<<<sm_blocks, 256>>>();
    k_agg1<<<N_NODES, 256>>>(b1);

    // ----- layer 2 -----
    k_aq<true><<<N_NODES, 256>>>((const float*)0, HC, HC);
    k_wmax<<<dim3(HC / 256, (HC + 31) / 32), 256>>>(W2, HC, 1);
    k_wsplitq<<<dim3(HC / 32, HC / 32), wsb>>>(W2, HC, HC, 1);
    k_igemm<<<gg, 256, IGSMEM>>>(HC, 1);
    k_att<<<att_blocks, 256>>>(as2, ad2);
    k_softmax<<<sm_blocks, 256>>>();
    k_agg2<<<N_NODES, 128>>>(b2, out);
}

// round 8
// speedup vs baseline: 3.4451x; 3.4451x over previous
#include <cuda_runtime.h>
#include <cuda_fp16.h>
#include <cstdint>

// ---------------- problem constants ----------------
#define N_NODES 10000
#define M_PAD   10112            // 79 * 128
#define N_EDGES 100000
#define EE      110000           // edges + self loops
#define G_IN    2000
#define K1_PAD  2048
#define H       20
#define C       128
#define HC      2560             // H * C
#define NEG_SLOPE 0.2f

// ---------------- scratch (device globals; no allocations) ----------------
__device__ float g_h[(size_t)N_NODES * HC];
__device__ float g_o[(size_t)N_NODES * HC];
__device__ float g_asrc[N_NODES * H];
__device__ float g_adst[N_NODES * H];
__device__ float g_alpha[(size_t)EE * H];
__device__ int   g_rowptr[N_NODES + 1];
__device__ int   g_deg[N_NODES];
__device__ int   g_fill[N_NODES];
__device__ int   g_csrc[EE];
__device__ int   g_is64;
__device__ int   g_esrc[N_EDGES];
__device__ int   g_edst[N_EDGES];
// fp16 operands: A hi/lo [m][kpad], W^T single [n][kpad]
__device__ __half g_ahi[(size_t)M_PAD * HC];
__device__ __half g_alo[(size_t)M_PAD * HC];
__device__ __half g_wt[(size_t)HC * HC];

// ---------------- helpers ----------------
__device__ __forceinline__ uint32_t smem_u32(const void* p) {
    uint32_t a;
    asm("{ .reg .u64 t; cvta.to.shared.u64 t, %1; cvt.u32.u64 %0, t; }" : "=r"(a) : "l"(p));
    return a;
}
#define SWZ(off) ((off) ^ (((off) >> 3) & 0x70))

__device__ __forceinline__ void cp16(uint32_t dst, const void* src) {
    asm volatile("cp.async.cg.shared.global [%0], [%1], 16;" :: "r"(dst), "l"(src) : "memory");
}
__device__ __forceinline__ void cp_commit() {
    asm volatile("cp.async.commit_group;" ::: "memory");
}
template <int X> __device__ __forceinline__ void cp_wait() {
    asm volatile("cp.async.wait_group %0;" :: "n"(X) : "memory");
}
#define LDSM4(r0, r1, r2, r3, addr) \
    asm volatile("ldmatrix.sync.aligned.m8n8.x4.shared.b16 {%0,%1,%2,%3}, [%4];" \
        : "=r"(r0), "=r"(r1), "=r"(r2), "=r"(r3) : "r"(addr))
#define MMA(c, a, b) \
    asm volatile("mma.sync.aligned.m16n8k16.row.col.f32.f16.f16.f32 " \
        "{%0,%1,%2,%3}, {%4,%5,%6,%7}, {%8,%9}, {%0,%1,%2,%3};" \
        : "+f"((c)[0]), "+f"((c)[1]), "+f"((c)[2]), "+f"((c)[3]) \
        : "r"((a)[0]), "r"((a)[1]), "r"((a)[2]), "r"((a)[3]), "r"((b)[0]), "r"((b)[1]))

// ---------------- edge dtype detection + normalization ----------------
__global__ void k_detect(const int* __restrict__ ei32) {
    __shared__ int any;
    if (threadIdx.x == 0) any = 0;
    __syncthreads();
    if (ei32[2 * threadIdx.x + 1] != 0) atomicOr(&any, 1);
    __syncthreads();
    if (threadIdx.x == 0) g_is64 = (any == 0) ? 1 : 0;
}
__global__ void k_norm(const int* __restrict__ ei32) {
    int e = blockIdx.x * blockDim.x + threadIdx.x;
    if (e >= N_EDGES) return;
    if (g_is64) { g_esrc[e] = ei32[2 * e]; g_edst[e] = ei32[2 * N_EDGES + 2 * e]; }
    else        { g_esrc[e] = ei32[e];     g_edst[e] = ei32[N_EDGES + e]; }
}

// ---------------- CSR build ----------------
__global__ void k_zero_deg() {
    int i = blockIdx.x * blockDim.x + threadIdx.x;
    if (i < N_NODES) g_deg[i] = 0;
}
__global__ void k_count() {
    int e = blockIdx.x * blockDim.x + threadIdx.x;
    if (e >= EE) return;
    int dst = (e < N_EDGES) ? g_edst[e] : (e - N_EDGES);
    atomicAdd(&g_deg[dst], 1);
}
__global__ void k_scan() {
    __shared__ int part[1024];
    int t = threadIdx.x;
    const int CH = (N_NODES + 1023) / 1024;
    int base = t * CH, s = 0;
    for (int i = 0; i < CH; i++) { int idx = base + i; if (idx < N_NODES) s += g_deg[idx]; }
    part[t] = s;
    __syncthreads();
    for (int o = 1; o < 1024; o <<= 1) {
        int v = (t >= o) ? part[t - o] : 0;
        __syncthreads(); part[t] += v; __syncthreads();
    }
    int run = (t > 0) ? part[t - 1] : 0;
    for (int i = 0; i < CH; i++) {
        int idx = base + i;
        if (idx < N_NODES) { g_rowptr[idx] = run; g_fill[idx] = run; run += g_deg[idx]; }
    }
    if (t == 1023) g_rowptr[N_NODES] = part[1023];
}
__global__ void k_scatter() {
    int e = blockIdx.x * blockDim.x + threadIdx.x;
    if (e >= EE) return;
    int src, dst;
    if (e < N_EDGES) { src = g_esrc[e]; dst = g_edst[e]; }
    else             { src = e - N_EDGES; dst = src; }
    int pos = atomicAdd(&g_fill[dst], 1);
    g_csrc[pos] = src;
}

// ---------------- activation split: g_ahi/g_alo[m][kpad] = fp16split(A[m][k]) ----------------
template <bool LAYER2>
__global__ void k_asplit(const float* __restrict__ Aext, int K, int KPAD) {
    const float* __restrict__ A = LAYER2 ? (const float*)g_o : Aext;
    int idx = blockIdx.x * blockDim.x + threadIdx.x;
    int rowlen4 = KPAD >> 2;
    if (idx >= N_NODES * rowlen4) return;
    int row = idx / rowlen4;
    int c4  = (idx - row * rowlen4) << 2;
    float v[4];
    #pragma unroll
    for (int j = 0; j < 4; j++) v[j] = (c4 + j < K) ? A[(size_t)row * K + c4 + j] : 0.f;
    uint32_t hw[2], lw[2];
    #pragma unroll
    for (int j = 0; j < 2; j++) {
        __half h0 = __float2half_rn(v[2 * j]);
        __half h1 = __float2half_rn(v[2 * j + 1]);
        __half l0 = __float2half_rn(v[2 * j] - __half2float(h0));
        __half l1 = __float2half_rn(v[2 * j + 1] - __half2float(h1));
        hw[j] = (uint32_t)__half_as_ushort(h0) | ((uint32_t)__half_as_ushort(h1) << 16);
        lw[j] = (uint32_t)__half_as_ushort(l0) | ((uint32_t)__half_as_ushort(l1) << 16);
    }
    size_t o = (size_t)row * KPAD + c4;
    *(uint2*)&g_ahi[o] = make_uint2(hw[0], hw[1]);
    *(uint2*)&g_alo[o] = make_uint2(lw[0], lw[1]);
}

// ---------------- W transpose to fp16: g_wt[n][kpad] = fp16(W[k][n]) ----------------
__global__ void k_wsplit(const float* __restrict__ W, int K, int KPAD) {
    __shared__ float tile[32][33];
    int n0 = blockIdx.y * 32, k0 = blockIdx.x * 32;
    int tx = threadIdx.x, ty = threadIdx.y;     // (32, 8)
    #pragma unroll
    for (int s = 0; s < 32; s += 8) {
        int k = k0 + ty + s;
        tile[ty + s][tx] = (k < K) ? W[(size_t)k * HC + n0 + tx] : 0.f;
    }
    __syncthreads();
    #pragma unroll
    for (int s = 0; s < 32; s += 8) {
        int n = n0 + ty + s;
        int k = k0 + tx;
        g_wt[(size_t)n * KPAD + k] = __float2half_rn(tile[tx][ty + s]);
    }
}

// ---------------- fp16 2-term HMMA GEMM: g_h[M][HC] = A @ W ----------------
// CTA tile 128x256, K staged 64, 3-stage cp.async pipeline, warp tile 64x64.
#define STG3    65536             // AHI 16K | ALO 16K | B 32K
#define OFF_ALO 16384
#define OFF_B   32768
#define GSMEM   (3 * STG3)        // 192 KB

__global__ __launch_bounds__(256, 1)
void k_hgemm(int kpad)
{
    extern __shared__ char smem[];
    uint32_t sb = smem_u32(smem);
    int tid  = threadIdx.x;
    int lane = tid & 31;
    int wid  = tid >> 5;
    int wr   = wid >> 2;            // 0..1  (64-row slabs)
    int wc   = wid & 3;             // 0..3  (64-col slabs)
    int row0 = blockIdx.y * 128;
    int col0 = blockIdx.x * 256;
    int nkb  = kpad >> 6;

    float acc[4][8][4];
    #pragma unroll
    for (int i = 0; i < 4; i++)
        #pragma unroll
        for (int j = 0; j < 8; j++)
            #pragma unroll
            for (int q = 0; q < 4; q++) acc[i][j][q] = 0.f;

    // ---- stage issue: 16 cp.async per thread (64 KB) ----
    auto issue = [&](int kb) {
        int kt = kb << 6;
        uint32_t st = sb + (kb % 3) * STG3;
        #pragma unroll
        for (int i = 0; i < 4; i++) {                 // A hi+lo: 128 rows
            int idx = i * 256 + tid;
            int r = idx >> 3, c = idx & 7;
            uint32_t off = SWZ((uint32_t)(r * 128 + c * 16));
            size_t ga = (size_t)(row0 + r) * kpad + kt + c * 8;
            cp16(st + off,           g_ahi + ga);
            cp16(st + OFF_ALO + off, g_alo + ga);
        }
        #pragma unroll
        for (int i = 0; i < 8; i++) {                 // B: 256 rows
            int idx = i * 256 + tid;
            int r = idx >> 3, c = idx & 7;
            uint32_t off = SWZ((uint32_t)(r * 128 + c * 16));
            size_t gb = (size_t)(col0 + r) * kpad + kt + c * 8;
            cp16(st + OFF_B + off, g_wt + gb);
        }
    };

    issue(0); cp_commit();
    if (nkb > 1) issue(1);
    cp_commit();

    for (int kb = 0; kb < nkb; kb++) {
        cp_wait<1>();
        __syncthreads();
        if (kb + 2 < nkb) issue(kb + 2);
        cp_commit();

        uint32_t tb = sb + (kb % 3) * STG3;
        #pragma unroll
        for (int k16 = 0; k16 < 4; k16++) {
            uint32_t ah[4][4], al[4][4];
            int arow = wr * 64 + (lane & 15);
            uint32_t acol = (uint32_t)(k16 * 32 + (lane >> 4) * 16);
            #pragma unroll
            for (int mt = 0; mt < 4; mt++) {
                uint32_t off = SWZ((uint32_t)((arow + mt * 16) * 128) + acol);
                LDSM4(ah[mt][0], ah[mt][1], ah[mt][2], ah[mt][3], tb + off);
                LDSM4(al[mt][0], al[mt][1], al[mt][2], al[mt][3], tb + OFF_ALO + off);
            }
            int mi = lane >> 3;
            int brow = wc * 64 + ((mi >> 1) << 3) + (lane & 7);
            uint32_t bcol = (uint32_t)(k16 * 32 + (mi & 1) * 16);
            #pragma unroll
            for (int half = 0; half < 2; half++) {
                uint32_t bh[4][2];
                #pragma unroll
                for (int q = 0; q < 2; q++) {
                    int nt2 = half * 2 + q;
                    uint32_t off = SWZ((uint32_t)((brow + nt2 * 16) * 128) + bcol);
                    LDSM4(bh[q * 2][0], bh[q * 2][1], bh[q * 2 + 1][0], bh[q * 2 + 1][1],
                          tb + OFF_B + off);
                }
                #pragma unroll
                for (int mt = 0; mt < 4; mt++)
                    #pragma unroll
                    for (int ntl = 0; ntl < 4; ntl++) {
                        int nt = half * 4 + ntl;
                        MMA(acc[mt][nt], ah[mt], bh[ntl]);
                        MMA(acc[mt][nt], al[mt], bh[ntl]);
                    }
            }
        }
    }

    // ---- epilogue ----
    #pragma unroll
    for (int mt = 0; mt < 4; mt++) {
        int gr = row0 + wr * 64 + mt * 16 + (lane >> 2);
        #pragma unroll
        for (int nt = 0; nt < 8; nt++) {
            int gc = col0 + wc * 64 + nt * 8 + (lane & 3) * 2;
            if (gr < N_NODES)
                *(float2*)&g_h[(size_t)gr * HC + gc] = make_float2(acc[mt][nt][0], acc[mt][nt][1]);
            if (gr + 8 < N_NODES)
                *(float2*)&g_h[(size_t)(gr + 8) * HC + gc] = make_float2(acc[mt][nt][2], acc[mt][nt][3]);
        }
    }
}

// ---------------- attention scores ----------------
__global__ void k_att(const float* __restrict__ wsrc,
                      const float* __restrict__ wdst)
{
    int gw   = (blockIdx.x * blockDim.x + threadIdx.x) >> 5;
    int lane = threadIdx.x & 31;
    if (gw >= N_NODES * H) return;
    int n  = gw / H;
    int hh = gw - n * H;
    const float* hp = g_h + (size_t)n * HC + hh * C;
    const float* ws = wsrc + hh * C;
    const float* wd = wdst + hh * C;
    float s1 = 0.f, s2 = 0.f;
    #pragma unroll
    for (int i = 0; i < 4; i++) {
        float v = hp[lane + i * 32];
        s1 += v * __ldg(&ws[lane + i * 32]);
        s2 += v * __ldg(&wd[lane + i * 32]);
    }
    #pragma unroll
    for (int o = 16; o; o >>= 1) {
        s1 += __shfl_down_sync(0xffffffffu, s1, o);
        s2 += __shfl_down_sync(0xffffffffu, s2, o);
    }
    if (lane == 0) { g_asrc[gw] = s1; g_adst[gw] = s2; }
}

// ---------------- per-(dst,head) softmax ----------------
__global__ void k_softmax() {
    int idx = blockIdx.x * blockDim.x + threadIdx.x;
    if (idx >= N_NODES * H) return;
    int dst = idx / H;
    int hh  = idx - dst * H;
    float ad = g_adst[dst * H + hh];
    int p0 = g_rowptr[dst], p1 = g_rowptr[dst + 1];
    float m = -1e30f;
    for (int p = p0; p < p1; p++) {
        int s = g_csrc[p];
        float ev = g_asrc[s * H + hh] + ad;
        ev = (ev > 0.f) ? ev : NEG_SLOPE * ev;
        g_alpha[(size_t)p * H + hh] = ev;
        m = fmaxf(m, ev);
    }
    float sum = 0.f;
    for (int p = p0; p < p1; p++) {
        float ex = __expf(g_alpha[(size_t)p * H + hh] - m);
        g_alpha[(size_t)p * H + hh] = ex;
        sum += ex;
    }
    float inv = 1.f / sum;
    for (int p = p0; p < p1; p++) g_alpha[(size_t)p * H + hh] *= inv;
}

// ---------------- layer-1 aggregation ----------------
__global__ __launch_bounds__(256)
void k_agg1(const float* __restrict__ b1)
{
    __shared__ float sal[H];
    int dst = blockIdx.x;
    int t   = threadIdx.x;
    int p0 = g_rowptr[dst], p1 = g_rowptr[dst + 1];
    float acc[10];
    #pragma unroll
    for (int j = 0; j < 10; j++) acc[j] = 0.f;

    for (int p = p0; p < p1; p++) {
        if (t < H) sal[t] = g_alpha[(size_t)p * H + t];
        __syncthreads();
        const float* hs = g_h + (size_t)g_csrc[p] * HC;
        #pragma unroll
        for (int j = 0; j < 10; j++) {
            int c = t + j * 256;
            acc[j] += sal[c >> 7] * hs[c];
        }
        __syncthreads();
    }
    float* op = g_o + (size_t)dst * HC;
    #pragma unroll
    for (int j = 0; j < 10; j++) {
        int c = t + j * 256;
        float v = acc[j] + b1[c];
        op[c] = (v > 0.f) ? v : 0.f;
    }
}

// ---------------- layer-2 aggregation ----------------
__global__ __launch_bounds__(128)
void k_agg2(const float* __restrict__ b2, float* __restrict__ out)
{
    __shared__ float sal[H];
    int dst = blockIdx.x;
    int t   = threadIdx.x;
    int p0 = g_rowptr[dst], p1 = g_rowptr[dst + 1];
    float acc = 0.f;
    for (int p = p0; p < p1; p++) {
        if (t < H) sal[t] = g_alpha[(size_t)p * H + t];
        __syncthreads();
        const float* hs = g_h + (size_t)g_csrc[p] * HC;
        #pragma unroll
        for (int hh = 0; hh < H; hh++) acc += sal[hh] * hs[hh * C + t];
        __syncthreads();
    }
    float v = acc * (1.f / (float)H) + b2[t];
    out[dst * C + t] = (v > 0.f) ? v : 0.f;
}

// ---------------- launch ----------------
extern "C" void kernel_launch(void* const* d_in, const int* in_sizes, int n_in,
                              void* d_out, int out_size)
{
    const float* x   = (const float*)d_in[0];
    const int*   ei  = (const int*)d_in[1];
    const float* W1  = (const float*)d_in[2];
    const float* as1 = (const float*)d_in[3];
    const float* ad1 = (const float*)d_in[4];
    const float* b1  = (const float*)d_in[5];
    const float* W2  = (const float*)d_in[6];
    const float* as2 = (const float*)d_in[7];
    const float* ad2 = (const float*)d_in[8];
    const float* b2  = (const float*)d_in[9];
    float* out = (float*)d_out;

    cudaFuncSetAttribute(k_hgemm, cudaFuncAttributeMaxDynamicSharedMemorySize, GSMEM);

    dim3 gg(HC / 256, M_PAD / 128);                 // (10, 79)
    int att_blocks = (N_NODES * H * 32 + 255) / 256;
    int sm_blocks  = (N_NODES * H + 255) / 256;
    dim3 wsb(32, 8);

    // ----- layer 1 (k_hgemm at launch #4 so ncu's fixed capture hits it) -----
    int a1blocks = (N_NODES * (K1_PAD / 4) + 255) / 256;
    k_asplit<false><<<a1blocks, 256>>>(x, G_IN, K1_PAD);             // 1
    k_wsplit<<<dim3(K1_PAD / 32, HC / 32), wsb>>>(W1, G_IN, K1_PAD); // 2
    k_detect<<<1, 256>>>(ei);                                        // 3
    k_hgemm<<<gg, 256, GSMEM>>>(K1_PAD);                             // 4
    // edge normalization + CSR build
    k_norm  <<<(N_EDGES + 255) / 256, 256>>>(ei);
    k_zero_deg<<<(N_NODES + 255) / 256, 256>>>();
    k_count  <<<(EE + 255) / 256, 256>>>();
    k_scan   <<<1, 1024>>>();
    k_scatter<<<(EE + 255) / 256, 256>>>();
    // layer-1 edge phase
    k_att<<<att_blocks, 256>>>(as1, ad1);
    k_softmax<<<sm_blocks, 256>>>();
    k_agg1<<<N_NODES, 256>>>(b1);

    // ----- layer 2 -----
    int a2blocks = (N_NODES * (HC / 4) + 255) / 256;
    k_asplit<true><<<a2blocks, 256>>>((const float*)0, HC, HC);
    k_wsplit<<<dim3(HC / 32, HC / 32), wsb>>>(W2, HC, HC);
    k_hgemm<<<gg, 256, GSMEM>>>(HC);
    k_att<<<att_blocks, 256>>>(as2, ad2);
    k_softmax<<<sm_blocks, 256>>>();
    k_agg2<<<N_NODES, 128>>>(b2, out);
}

// round 9
// speedup vs baseline: 5.0371x; 1.4621x over previous
#include <cuda_runtime.h>
#include <cuda_fp16.h>
#include <cstdint>

// ---------------- problem constants ----------------
#define N_NODES 10000
#define M_PAD   10112            // 79 * 128
#define N_EDGES 100000
#define EE      110000           // edges + self loops
#define G_IN    2000
#define K1_PAD  2048
#define H       20
#define C       128
#define HC      2560             // H * C
#define NEG_SLOPE 0.2f

// ---------------- scratch (device globals; no allocations) ----------------
__device__ float g_h[(size_t)N_NODES * HC];
__device__ float g_o[(size_t)N_NODES * HC];
__device__ float g_asrc[N_NODES * H];
__device__ float g_adst[N_NODES * H];
__device__ float g_alpha[(size_t)EE * H];
__device__ int   g_rowptr[N_NODES + 1];
__device__ int   g_deg[N_NODES];
__device__ int   g_fill[N_NODES];
__device__ int   g_csrc[EE];
__device__ int   g_is64;
__device__ int   g_esrc[N_EDGES];
__device__ int   g_edst[N_EDGES];
// fp16 operands: A [m][kpad], W^T [n][kpad]
__device__ __half g_ah[(size_t)M_PAD * HC];
__device__ __half g_wt[(size_t)HC * HC];

// ---------------- helpers ----------------
__device__ __forceinline__ uint32_t smem_u32(const void* p) {
    uint32_t a;
    asm("{ .reg .u64 t; cvta.to.shared.u64 t, %1; cvt.u32.u64 %0, t; }" : "=r"(a) : "l"(p));
    return a;
}
#define SWZ(off) ((off) ^ (((off) >> 3) & 0x70))

__device__ __forceinline__ void cp16(uint32_t dst, const void* src) {
    asm volatile("cp.async.cg.shared.global [%0], [%1], 16;" :: "r"(dst), "l"(src) : "memory");
}
__device__ __forceinline__ void cp_commit() {
    asm volatile("cp.async.commit_group;" ::: "memory");
}
template <int X> __device__ __forceinline__ void cp_wait() {
    asm volatile("cp.async.wait_group %0;" :: "n"(X) : "memory");
}
#define LDSM4(r0, r1, r2, r3, addr) \
    asm volatile("ldmatrix.sync.aligned.m8n8.x4.shared.b16 {%0,%1,%2,%3}, [%4];" \
        : "=r"(r0), "=r"(r1), "=r"(r2), "=r"(r3) : "r"(addr))
#define MMA(c, a, b) \
    asm volatile("mma.sync.aligned.m16n8k16.row.col.f32.f16.f16.f32 " \
        "{%0,%1,%2,%3}, {%4,%5,%6,%7}, {%8,%9}, {%0,%1,%2,%3};" \
        : "+f"((c)[0]), "+f"((c)[1]), "+f"((c)[2]), "+f"((c)[3]) \
        : "r"((a)[0]), "r"((a)[1]), "r"((a)[2]), "r"((a)[3]), "r"((b)[0]), "r"((b)[1]))

// ---------------- edge dtype detection + normalization ----------------
__global__ void k_detect(const int* __restrict__ ei32) {
    __shared__ int any;
    if (threadIdx.x == 0) any = 0;
    __syncthreads();
    if (ei32[2 * threadIdx.x + 1] != 0) atomicOr(&any, 1);
    __syncthreads();
    if (threadIdx.x == 0) g_is64 = (any == 0) ? 1 : 0;
}
__global__ void k_norm(const int* __restrict__ ei32) {
    int e = blockIdx.x * blockDim.x + threadIdx.x;
    if (e >= N_EDGES) return;
    if (g_is64) { g_esrc[e] = ei32[2 * e]; g_edst[e] = ei32[2 * N_EDGES + 2 * e]; }
    else        { g_esrc[e] = ei32[e];     g_edst[e] = ei32[N_EDGES + e]; }
}

// ---------------- CSR build ----------------
__global__ void k_zero_deg() {
    int i = blockIdx.x * blockDim.x + threadIdx.x;
    if (i < N_NODES) g_deg[i] = 0;
}
__global__ void k_count() {
    int e = blockIdx.x * blockDim.x + threadIdx.x;
    if (e >= EE) return;
    int dst = (e < N_EDGES) ? g_edst[e] : (e - N_EDGES);
    atomicAdd(&g_deg[dst], 1);
}
__global__ void k_scan() {
    __shared__ int part[1024];
    int t = threadIdx.x;
    const int CH = (N_NODES + 1023) / 1024;
    int base = t * CH, s = 0;
    for (int i = 0; i < CH; i++) { int idx = base + i; if (idx < N_NODES) s += g_deg[idx]; }
    part[t] = s;
    __syncthreads();
    for (int o = 1; o < 1024; o <<= 1) {
        int v = (t >= o) ? part[t - o] : 0;
        __syncthreads(); part[t] += v; __syncthreads();
    }
    int run = (t > 0) ? part[t - 1] : 0;
    for (int i = 0; i < CH; i++) {
        int idx = base + i;
        if (idx < N_NODES) { g_rowptr[idx] = run; g_fill[idx] = run; run += g_deg[idx]; }
    }
    if (t == 1023) g_rowptr[N_NODES] = part[1023];
}
__global__ void k_scatter() {
    int e = blockIdx.x * blockDim.x + threadIdx.x;
    if (e >= EE) return;
    int src, dst;
    if (e < N_EDGES) { src = g_esrc[e]; dst = g_edst[e]; }
    else             { src = e - N_EDGES; dst = src; }
    int pos = atomicAdd(&g_fill[dst], 1);
    g_csrc[pos] = src;
}

// ---------------- activation convert: g_ah[m][kpad] = fp16(A[m][k]) ----------------
template <bool LAYER2>
__global__ void k_acvt(const float* __restrict__ Aext, int K, int KPAD) {
    const float* __restrict__ A = LAYER2 ? (const float*)g_o : Aext;
    int idx = blockIdx.x * blockDim.x + threadIdx.x;
    int rowlen4 = KPAD >> 2;
    if (idx >= N_NODES * rowlen4) return;
    int row = idx / rowlen4;
    int c4  = (idx - row * rowlen4) << 2;
    float v[4];
    #pragma unroll
    for (int j = 0; j < 4; j++) v[j] = (c4 + j < K) ? A[(size_t)row * K + c4 + j] : 0.f;
    uint32_t w0 = (uint32_t)__half_as_ushort(__float2half_rn(v[0]))
                | ((uint32_t)__half_as_ushort(__float2half_rn(v[1])) << 16);
    uint32_t w1 = (uint32_t)__half_as_ushort(__float2half_rn(v[2]))
                | ((uint32_t)__half_as_ushort(__float2half_rn(v[3])) << 16);
    *(uint2*)&g_ah[(size_t)row * KPAD + c4] = make_uint2(w0, w1);
}

// ---------------- W transpose to fp16: g_wt[n][kpad] = fp16(W[k][n]) ----------------
__global__ void k_wsplit(const float* __restrict__ W, int K, int KPAD) {
    __shared__ float tile[32][33];
    int n0 = blockIdx.y * 32, k0 = blockIdx.x * 32;
    int tx = threadIdx.x, ty = threadIdx.y;     // (32, 8)
    #pragma unroll
    for (int s = 0; s < 32; s += 8) {
        int k = k0 + ty + s;
        tile[ty + s][tx] = (k < K) ? W[(size_t)k * HC + n0 + tx] : 0.f;
    }
    __syncthreads();
    #pragma unroll
    for (int s = 0; s < 32; s += 8) {
        int n = n0 + ty + s;
        int k = k0 + tx;
        g_wt[(size_t)n * KPAD + k] = __float2half_rn(tile[tx][ty + s]);
    }
}

// ---------------- fp16 HMMA GEMM: g_h[M][HC] = A @ W ----------------
// CTA tile 128x256, K staged 64, 4-stage cp.async pipeline, warp tile 64x64.
#define STG4   49152              // A 16K | B 32K
#define OFF_B  16384
#define GSMEM  (4 * STG4)         // 192 KB

__global__ __launch_bounds__(256, 1)
void k_hgemm(int kpad)
{
    extern __shared__ char smem[];
    uint32_t sb = smem_u32(smem);
    int tid  = threadIdx.x;
    int lane = tid & 31;
    int wid  = tid >> 5;
    int wr   = wid >> 2;            // 0..1  (64-row slabs)
    int wc   = wid & 3;             // 0..3  (64-col slabs)
    int row0 = blockIdx.y * 128;
    int col0 = blockIdx.x * 256;
    int nkb  = kpad >> 6;

    float acc[4][8][4];
    #pragma unroll
    for (int i = 0; i < 4; i++)
        #pragma unroll
        for (int j = 0; j < 8; j++)
            #pragma unroll
            for (int q = 0; q < 4; q++) acc[i][j][q] = 0.f;

    // ---- stage issue: 12 cp.async per thread (48 KB) ----
    auto issue = [&](int kb) {
        int kt = kb << 6;
        uint32_t st = sb + (kb & 3) * STG4;
        #pragma unroll
        for (int i = 0; i < 4; i++) {                 // A: 128 rows
            int idx = i * 256 + tid;
            int r = idx >> 3, c = idx & 7;
            uint32_t off = SWZ((uint32_t)(r * 128 + c * 16));
            cp16(st + off, g_ah + (size_t)(row0 + r) * kpad + kt + c * 8);
        }
        #pragma unroll
        for (int i = 0; i < 8; i++) {                 // B: 256 rows
            int idx = i * 256 + tid;
            int r = idx >> 3, c = idx & 7;
            uint32_t off = SWZ((uint32_t)(r * 128 + c * 16));
            cp16(st + OFF_B + off, g_wt + (size_t)(col0 + r) * kpad + kt + c * 8);
        }
    };

    issue(0); cp_commit();
    if (nkb > 1) issue(1);
    cp_commit();
    if (nkb > 2) issue(2);
    cp_commit();

    for (int kb = 0; kb < nkb; kb++) {
        cp_wait<2>();
        __syncthreads();
        if (kb + 3 < nkb) issue(kb + 3);
        cp_commit();

        uint32_t tb = sb + (kb & 3) * STG4;
        #pragma unroll
        for (int k16 = 0; k16 < 4; k16++) {
            uint32_t ah[4][4];
            int arow = wr * 64 + (lane & 15);
            uint32_t acol = (uint32_t)(k16 * 32 + (lane >> 4) * 16);
            #pragma unroll
            for (int mt = 0; mt < 4; mt++) {
                uint32_t off = SWZ((uint32_t)((arow + mt * 16) * 128) + acol);
                LDSM4(ah[mt][0], ah[mt][1], ah[mt][2], ah[mt][3], tb + off);
            }
            int mi = lane >> 3;
            int brow = wc * 64 + ((mi >> 1) << 3) + (lane & 7);
            uint32_t bcol = (uint32_t)(k16 * 32 + (mi & 1) * 16);
            #pragma unroll
            for (int half = 0; half < 2; half++) {
                uint32_t bh[4][2];
                #pragma unroll
                for (int q = 0; q < 2; q++) {
                    int nt2 = half * 2 + q;
                    uint32_t off = SWZ((uint32_t)((brow + nt2 * 16) * 128) + bcol);
                    LDSM4(bh[q * 2][0], bh[q * 2][1], bh[q * 2 + 1][0], bh[q * 2 + 1][1],
                          tb + OFF_B + off);
                }
                #pragma unroll
                for (int mt = 0; mt < 4; mt++)
                    #pragma unroll
                    for (int ntl = 0; ntl < 4; ntl++)
                        MMA(acc[mt][half * 4 + ntl], ah[mt], bh[ntl]);
            }
        }
    }

    // ---- epilogue ----
    #pragma unroll
    for (int mt = 0; mt < 4; mt++) {
        int gr = row0 + wr * 64 + mt * 16 + (lane >> 2);
        #pragma unroll
        for (int nt = 0; nt < 8; nt++) {
            int gc = col0 + wc * 64 + nt * 8 + (lane & 3) * 2;
            if (gr < N_NODES)
                *(float2*)&g_h[(size_t)gr * HC + gc] = make_float2(acc[mt][nt][0], acc[mt][nt][1]);
            if (gr + 8 < N_NODES)
                *(float2*)&g_h[(size_t)(gr + 8) * HC + gc] = make_float2(acc[mt][nt][2], acc[mt][nt][3]);
        }
    }
}

// ---------------- attention scores ----------------
__global__ void k_att(const float* __restrict__ wsrc,
                      const float* __restrict__ wdst)
{
    int gw   = (blockIdx.x * blockDim.x + threadIdx.x) >> 5;
    int lane = threadIdx.x & 31;
    if (gw >= N_NODES * H) return;
    int n  = gw / H;
    int hh = gw - n * H;
    const float* hp = g_h + (size_t)n * HC + hh * C;
    const float* ws = wsrc + hh * C;
    const float* wd = wdst + hh * C;
    float s1 = 0.f, s2 = 0.f;
    #pragma unroll
    for (int i = 0; i < 4; i++) {
        float v = hp[lane + i * 32];
        s1 += v * __ldg(&ws[lane + i * 32]);
        s2 += v * __ldg(&wd[lane + i * 32]);
    }
    #pragma unroll
    for (int o = 16; o; o >>= 1) {
        s1 += __shfl_down_sync(0xffffffffu, s1, o);
        s2 += __shfl_down_sync(0xffffffffu, s2, o);
    }
    if (lane == 0) { g_asrc[gw] = s1; g_adst[gw] = s2; }
}

// ---------------- per-(dst,head) softmax ----------------
__global__ void k_softmax() {
    int idx = blockIdx.x * blockDim.x + threadIdx.x;
    if (idx >= N_NODES * H) return;
    int dst = idx / H;
    int hh  = idx - dst * H;
    float ad = g_adst[dst * H + hh];
    int p0 = g_rowptr[dst], p1 = g_rowptr[dst + 1];
    float m = -1e30f;
    for (int p = p0; p < p1; p++) {
        int s = g_csrc[p];
        float ev = g_asrc[s * H + hh] + ad;
        ev = (ev > 0.f) ? ev : NEG_SLOPE * ev;
        g_alpha[(size_t)p * H + hh] = ev;
        m = fmaxf(m, ev);
    }
    float sum = 0.f;
    for (int p = p0; p < p1; p++) {
        float ex = __expf(g_alpha[(size_t)p * H + hh] - m);
        g_alpha[(size_t)p * H + hh] = ex;
        sum += ex;
    }
    float inv = 1.f / sum;
    for (int p = p0; p < p1; p++) g_alpha[(size_t)p * H + hh] *= inv;
}

// ---------------- layer-1 aggregation ----------------
__global__ __launch_bounds__(256)
void k_agg1(const float* __restrict__ b1)
{
    __shared__ float sal[H];
    int dst = blockIdx.x;
    int t   = threadIdx.x;
    int p0 = g_rowptr[dst], p1 = g_rowptr[dst + 1];
    float acc[10];
    #pragma unroll
    for (int j = 0; j < 10; j++) acc[j] = 0.f;

    for (int p = p0; p < p1; p++) {
        if (t < H) sal[t] = g_alpha[(size_t)p * H + t];
        __syncthreads();
        const float* hs = g_h + (size_t)g_csrc[p] * HC;
        #pragma unroll
        for (int j = 0; j < 10; j++) {
            int c = t + j * 256;
            acc[j] += sal[c >> 7] * hs[c];
        }
        __syncthreads();
    }
    float* op = g_o + (size_t)dst * HC;
    #pragma unroll
    for (int j = 0; j < 10; j++) {
        int c = t + j * 256;
        float v = acc[j] + b1[c];
        op[c] = (v > 0.f) ? v : 0.f;
    }
}

// ---------------- layer-2 aggregation ----------------
__global__ __launch_bounds__(128)
void k_agg2(const float* __restrict__ b2, float* __restrict__ out)
{
    __shared__ float sal[H];
    int dst = blockIdx.x;
    int t   = threadIdx.x;
    int p0 = g_rowptr[dst], p1 = g_rowptr[dst + 1];
    float acc = 0.f;
    for (int p = p0; p < p1; p++) {
        if (t < H) sal[t] = g_alpha[(size_t)p * H + t];
        __syncthreads();
        const float* hs = g_h + (size_t)g_csrc[p] * HC;
        #pragma unroll
        for (int hh = 0; hh < H; hh++) acc += sal[hh] * hs[hh * C + t];
        __syncthreads();
    }
    float v = acc * (1.f / (float)H) + b2[t];
    out[dst * C + t] = (v > 0.f) ? v : 0.f;
}

// ---------------- launch ----------------
extern "C" void kernel_launch(void* const* d_in, const int* in_sizes, int n_in,
                              void* d_out, int out_size)
{
    const float* x   = (const float*)d_in[0];
    const int*   ei  = (const int*)d_in[1];
    const float* W1  = (const float*)d_in[2];
    const float* as1 = (const float*)d_in[3];
    const float* ad1 = (const float*)d_in[4];
    const float* b1  = (const float*)d_in[5];
    const float* W2  = (const float*)d_in[6];
    const float* as2 = (const float*)d_in[7];
    const float* ad2 = (const float*)d_in[8];
    const float* b2  = (const float*)d_in[9];
    float* out = (float*)d_out;

    cudaFuncSetAttribute(k_hgemm, cudaFuncAttributeMaxDynamicSharedMemorySize, GSMEM);

    dim3 gg(HC / 256, M_PAD / 128);                 // (10, 79)
    int att_blocks = (N_NODES * H * 32 + 255) / 256;
    int sm_blocks  = (N_NODES * H + 255) / 256;
    dim3 wsb(32, 8);

    // ----- layer 1 (k_hgemm at launch #4 so ncu's fixed capture hits it) -----
    int a1blocks = (N_NODES * (K1_PAD / 4) + 255) / 256;
    k_acvt<false><<<a1blocks, 256>>>(x, G_IN, K1_PAD);               // 1
    k_wsplit<<<dim3(K1_PAD / 32, HC / 32), wsb>>>(W1, G_IN, K1_PAD); // 2
    k_detect<<<1, 256>>>(ei);                                        // 3
    k_hgemm<<<gg, 256, GSMEM>>>(K1_PAD);                             // 4
    // edge normalization + CSR build
    k_norm  <<<(N_EDGES + 255) / 256, 256>>>(ei);
    k_zero_deg<<<(N_NODES + 255) / 256, 256>>>();
    k_count  <<<(EE + 255) / 256, 256>>>();
    k_scan   <<<1, 1024>>>();
    k_scatter<<<(EE + 255) / 256, 256>>>();
    // layer-1 edge phase
    k_att<<<att_blocks, 256>>>(as1, ad1);
    k_softmax<<<sm_blocks, 256>>>();
    k_agg1<<<N_NODES, 256>>>(b1);

    // ----- layer 2 -----
    int a2blocks = (N_NODES * (HC / 4) + 255) / 256;
    k_acvt<true><<<a2blocks, 256>>>((const float*)0, HC, HC);
    k_wsplit<<<dim3(HC / 32, HC / 32), wsb>>>(W2, HC, HC);
    k_hgemm<<<gg, 256, GSMEM>>>(HC);
    k_att<<<att_blocks, 256>>>(as2, ad2);
    k_softmax<<<sm_blocks, 256>>>();
    k_agg2<<<N_NODES, 128>>>(b2, out);
}

// round 10
// speedup vs baseline: 6.0057x; 1.1923x over previous
#include <cuda_runtime.h>
#include <cuda_fp16.h>
#include <cstdint>

// ---------------- problem constants ----------------
#define N_NODES 10000
#define M_PAD   10112            // 79 * 128
#define N_EDGES 100000
#define EE      110000           // edges + self loops
#define G_IN    2000
#define K1_PAD  2048
#define H       20
#define C       128
#define HC      2560             // H * C
#define NEG_SLOPE 0.2f

// ---------------- scratch (device globals; no allocations) ----------------
__device__ float  g_h[(size_t)N_NODES * HC];     // fp32 GEMM output (for k_att)
__device__ __half g_hh[(size_t)N_NODES * HC];    // fp16 mirror (for aggregations)
__device__ float  g_asrc[N_NODES * H];
__device__ float  g_adst[N_NODES * H];
__device__ float  g_alpha[(size_t)EE * H];
__device__ int    g_rowptr[N_NODES + 1];
__device__ int    g_deg[N_NODES];
__device__ int    g_fill[N_NODES];
__device__ int    g_csrc[EE];
__device__ int    g_is64;
__device__ int    g_esrc[N_EDGES];
__device__ int    g_edst[N_EDGES];
// fp16 GEMM operands: A [m][kpad], W^T [n][kpad]
__device__ __half g_ah[(size_t)M_PAD * HC];
__device__ __half g_wt[(size_t)HC * HC];

// ---------------- helpers ----------------
__device__ __forceinline__ uint32_t smem_u32(const void* p) {
    uint32_t a;
    asm("{ .reg .u64 t; cvta.to.shared.u64 t, %1; cvt.u32.u64 %0, t; }" : "=r"(a) : "l"(p));
    return a;
}
#define SWZ(off) ((off) ^ (((off) >> 3) & 0x70))

__device__ __forceinline__ void cp16(uint32_t dst, const void* src) {
    asm volatile("cp.async.cg.shared.global [%0], [%1], 16;" :: "r"(dst), "l"(src) : "memory");
}
__device__ __forceinline__ void cp_commit() {
    asm volatile("cp.async.commit_group;" ::: "memory");
}
template <int X> __device__ __forceinline__ void cp_wait() {
    asm volatile("cp.async.wait_group %0;" :: "n"(X) : "memory");
}
#define LDSM4(r0, r1, r2, r3, addr) \
    asm volatile("ldmatrix.sync.aligned.m8n8.x4.shared.b16 {%0,%1,%2,%3}, [%4];" \
        : "=r"(r0), "=r"(r1), "=r"(r2), "=r"(r3) : "r"(addr))
#define MMA(c, a, b) \
    asm volatile("mma.sync.aligned.m16n8k16.row.col.f32.f16.f16.f32 " \
        "{%0,%1,%2,%3}, {%4,%5,%6,%7}, {%8,%9}, {%0,%1,%2,%3};" \
        : "+f"((c)[0]), "+f"((c)[1]), "+f"((c)[2]), "+f"((c)[3]) \
        : "r"((a)[0]), "r"((a)[1]), "r"((a)[2]), "r"((a)[3]), "r"((b)[0]), "r"((b)[1]))

// ---------------- edge dtype detection + normalization ----------------
__global__ void k_detect(const int* __restrict__ ei32) {
    __shared__ int any;
    if (threadIdx.x == 0) any = 0;
    __syncthreads();
    if (ei32[2 * threadIdx.x + 1] != 0) atomicOr(&any, 1);
    __syncthreads();
    if (threadIdx.x == 0) g_is64 = (any == 0) ? 1 : 0;
}
__global__ void k_norm(const int* __restrict__ ei32) {
    int e = blockIdx.x * blockDim.x + threadIdx.x;
    if (e >= N_EDGES) return;
    if (g_is64) { g_esrc[e] = ei32[2 * e]; g_edst[e] = ei32[2 * N_EDGES + 2 * e]; }
    else        { g_esrc[e] = ei32[e];     g_edst[e] = ei32[N_EDGES + e]; }
}

// ---------------- CSR build ----------------
__global__ void k_zero_deg() {
    int i = blockIdx.x * blockDim.x + threadIdx.x;
    if (i < N_NODES) g_deg[i] = 0;
}
__global__ void k_count() {
    int e = blockIdx.x * blockDim.x + threadIdx.x;
    if (e >= EE) return;
    int dst = (e < N_EDGES) ? g_edst[e] : (e - N_EDGES);
    atomicAdd(&g_deg[dst], 1);
}
__global__ void k_scan() {
    __shared__ int part[1024];
    int t = threadIdx.x;
    const int CH = (N_NODES + 1023) / 1024;
    int base = t * CH, s = 0;
    for (int i = 0; i < CH; i++) { int idx = base + i; if (idx < N_NODES) s += g_deg[idx]; }
    part[t] = s;
    __syncthreads();
    for (int o = 1; o < 1024; o <<= 1) {
        int v = (t >= o) ? part[t - o] : 0;
        __syncthreads(); part[t] += v; __syncthreads();
    }
    int run = (t > 0) ? part[t - 1] : 0;
    for (int i = 0; i < CH; i++) {
        int idx = base + i;
        if (idx < N_NODES) { g_rowptr[idx] = run; g_fill[idx] = run; run += g_deg[idx]; }
    }
    if (t == 1023) g_rowptr[N_NODES] = part[1023];
}
__global__ void k_scatter() {
    int e = blockIdx.x * blockDim.x + threadIdx.x;
    if (e >= EE) return;
    int src, dst;
    if (e < N_EDGES) { src = g_esrc[e]; dst = g_edst[e]; }
    else             { src = e - N_EDGES; dst = src; }
    int pos = atomicAdd(&g_fill[dst], 1);
    g_csrc[pos] = src;
}

// ---------------- layer-1 activation convert: g_ah[m][kpad] = fp16(x[m][k]) ----------------
__global__ void k_acvt(const float* __restrict__ A, int K, int KPAD) {
    int idx = blockIdx.x * blockDim.x + threadIdx.x;
    int rowlen4 = KPAD >> 2;
    if (idx >= N_NODES * rowlen4) return;
    int row = idx / rowlen4;
    int c4  = (idx - row * rowlen4) << 2;
    float v[4];
    #pragma unroll
    for (int j = 0; j < 4; j++) v[j] = (c4 + j < K) ? A[(size_t)row * K + c4 + j] : 0.f;
    uint32_t w0 = (uint32_t)__half_as_ushort(__float2half_rn(v[0]))
                | ((uint32_t)__half_as_ushort(__float2half_rn(v[1])) << 16);
    uint32_t w1 = (uint32_t)__half_as_ushort(__float2half_rn(v[2]))
                | ((uint32_t)__half_as_ushort(__float2half_rn(v[3])) << 16);
    *(uint2*)&g_ah[(size_t)row * KPAD + c4] = make_uint2(w0, w1);
}

// ---------------- W transpose to fp16: g_wt[n][kpad] = fp16(W[k][n]) ----------------
__global__ void k_wsplit(const float* __restrict__ W, int K, int KPAD) {
    __shared__ float tile[32][33];
    int n0 = blockIdx.y * 32, k0 = blockIdx.x * 32;
    int tx = threadIdx.x, ty = threadIdx.y;     // (32, 8)
    #pragma unroll
    for (int s = 0; s < 32; s += 8) {
        int k = k0 + ty + s;
        tile[ty + s][tx] = (k < K) ? W[(size_t)k * HC + n0 + tx] : 0.f;
    }
    __syncthreads();
    #pragma unroll
    for (int s = 0; s < 32; s += 8) {
        int n = n0 + ty + s;
        int k = k0 + tx;
        g_wt[(size_t)n * KPAD + k] = __float2half_rn(tile[tx][ty + s]);
    }
}

// ---------------- fp16 HMMA GEMM: g_h/g_hh[M][HC] = A @ W ----------------
// CTA tile 128x256, K staged 64, 4-stage cp.async pipeline, warp tile 64x64.
#define STG4   49152              // A 16K | B 32K
#define OFF_B  16384
#define GSMEM  (4 * STG4)         // 192 KB

__global__ __launch_bounds__(256, 1)
void k_hgemm(int kpad)
{
    extern __shared__ char smem[];
    uint32_t sb = smem_u32(smem);
    int tid  = threadIdx.x;
    int lane = tid & 31;
    int wid  = tid >> 5;
    int wr   = wid >> 2;
    int wc   = wid & 3;
    int row0 = blockIdx.y * 128;
    int col0 = blockIdx.x * 256;
    int nkb  = kpad >> 6;

    float acc[4][8][4];
    #pragma unroll
    for (int i = 0; i < 4; i++)
        #pragma unroll
        for (int j = 0; j < 8; j++)
            #pragma unroll
            for (int q = 0; q < 4; q++) acc[i][j][q] = 0.f;

    auto issue = [&](int kb) {
        int kt = kb << 6;
        uint32_t st = sb + (kb & 3) * STG4;
        #pragma unroll
        for (int i = 0; i < 4; i++) {
            int idx = i * 256 + tid;
            int r = idx >> 3, c = idx & 7;
            uint32_t off = SWZ((uint32_t)(r * 128 + c * 16));
            cp16(st + off, g_ah + (size_t)(row0 + r) * kpad + kt + c * 8);
        }
        #pragma unroll
        for (int i = 0; i < 8; i++) {
            int idx = i * 256 + tid;
            int r = idx >> 3, c = idx & 7;
            uint32_t off = SWZ((uint32_t)(r * 128 + c * 16));
            cp16(st + OFF_B + off, g_wt + (size_t)(col0 + r) * kpad + kt + c * 8);
        }
    };

    issue(0); cp_commit();
    if (nkb > 1) issue(1);
    cp_commit();
    if (nkb > 2) issue(2);
    cp_commit();

    for (int kb = 0; kb < nkb; kb++) {
        cp_wait<2>();
        __syncthreads();
        if (kb + 3 < nkb) issue(kb + 3);
        cp_commit();

        uint32_t tb = sb + (kb & 3) * STG4;
        #pragma unroll
        for (int k16 = 0; k16 < 4; k16++) {
            uint32_t ah[4][4];
            int arow = wr * 64 + (lane & 15);
            uint32_t acol = (uint32_t)(k16 * 32 + (lane >> 4) * 16);
            #pragma unroll
            for (int mt = 0; mt < 4; mt++) {
                uint32_t off = SWZ((uint32_t)((arow + mt * 16) * 128) + acol);
                LDSM4(ah[mt][0], ah[mt][1], ah[mt][2], ah[mt][3], tb + off);
            }
            int mi = lane >> 3;
            int brow = wc * 64 + ((mi >> 1) << 3) + (lane & 7);
            uint32_t bcol = (uint32_t)(k16 * 32 + (mi & 1) * 16);
            #pragma unroll
            for (int half = 0; half < 2; half++) {
                uint32_t bh[4][2];
                #pragma unroll
                for (int q = 0; q < 2; q++) {
                    int nt2 = half * 2 + q;
                    uint32_t off = SWZ((uint32_t)((brow + nt2 * 16) * 128) + bcol);
                    LDSM4(bh[q * 2][0], bh[q * 2][1], bh[q * 2 + 1][0], bh[q * 2 + 1][1],
                          tb + OFF_B + off);
                }
                #pragma unroll
                for (int mt = 0; mt < 4; mt++)
                    #pragma unroll
                    for (int ntl = 0; ntl < 4; ntl++)
                        MMA(acc[mt][half * 4 + ntl], ah[mt], bh[ntl]);
            }
        }
    }

    // ---- epilogue: fp32 (for k_att) + fp16 mirror (for aggregations) ----
    #pragma unroll
    for (int mt = 0; mt < 4; mt++) {
        int gr = row0 + wr * 64 + mt * 16 + (lane >> 2);
        #pragma unroll
        for (int nt = 0; nt < 8; nt++) {
            int gc = col0 + wc * 64 + nt * 8 + (lane & 3) * 2;
            if (gr < N_NODES) {
                *(float2*)&g_h[(size_t)gr * HC + gc] = make_float2(acc[mt][nt][0], acc[mt][nt][1]);
                *(__half2*)&g_hh[(size_t)gr * HC + gc] =
                    __floats2half2_rn(acc[mt][nt][0], acc[mt][nt][1]);
            }
            if (gr + 8 < N_NODES) {
                *(float2*)&g_h[(size_t)(gr + 8) * HC + gc] = make_float2(acc[mt][nt][2], acc[mt][nt][3]);
                *(__half2*)&g_hh[(size_t)(gr + 8) * HC + gc] =
                    __floats2half2_rn(acc[mt][nt][2], acc[mt][nt][3]);
            }
        }
    }
}

// ---------------- attention scores ----------------
__global__ void k_att(const float* __restrict__ wsrc,
                      const float* __restrict__ wdst)
{
    int gw   = (blockIdx.x * blockDim.x + threadIdx.x) >> 5;
    int lane = threadIdx.x & 31;
    if (gw >= N_NODES * H) return;
    int n  = gw / H;
    int hh = gw - n * H;
    const float* hp = g_h + (size_t)n * HC + hh * C;
    const float* ws = wsrc + hh * C;
    const float* wd = wdst + hh * C;
    float s1 = 0.f, s2 = 0.f;
    #pragma unroll
    for (int i = 0; i < 4; i++) {
        float v = hp[lane + i * 32];
        s1 += v * __ldg(&ws[lane + i * 32]);
        s2 += v * __ldg(&wd[lane + i * 32]);
    }
    #pragma unroll
    for (int o = 16; o; o >>= 1) {
        s1 += __shfl_down_sync(0xffffffffu, s1, o);
        s2 += __shfl_down_sync(0xffffffffu, s2, o);
    }
    if (lane == 0) { g_asrc[gw] = s1; g_adst[gw] = s2; }
}

// ---------------- per-(dst,head) softmax ----------------
__global__ void k_softmax() {
    int idx = blockIdx.x * blockDim.x + threadIdx.x;
    if (idx >= N_NODES * H) return;
    int dst = idx / H;
    int hh  = idx - dst * H;
    float ad = g_adst[dst * H + hh];
    int p0 = g_rowptr[dst], p1 = g_rowptr[dst + 1];
    float m = -1e30f;
    for (int p = p0; p < p1; p++) {
        int s = g_csrc[p];
        float ev = g_asrc[s * H + hh] + ad;
        ev = (ev > 0.f) ? ev : NEG_SLOPE * ev;
        g_alpha[(size_t)p * H + hh] = ev;
        m = fmaxf(m, ev);
    }
    float sum = 0.f;
    for (int p = p0; p < p1; p++) {
        float ex = __expf(g_alpha[(size_t)p * H + hh] - m);
        g_alpha[(size_t)p * H + hh] = ex;
        sum += ex;
    }
    float inv = 1.f / sum;
    for (int p = p0; p < p1; p++) g_alpha[(size_t)p * H + hh] *= inv;
}

// ---------------- layer-1 aggregation: g_ah[dst,:] = fp16(relu(sum alpha*hh[src,:] + b1)) ----------------
__global__ __launch_bounds__(320)
void k_agg1(const float* __restrict__ b1)
{
    int dst = blockIdx.x;
    int t   = threadIdx.x;          // 0..319
    int c8  = t * 8;                // 8 cols per thread (all within head t>>4)
    int hh  = t >> 4;
    int p0 = g_rowptr[dst], p1 = g_rowptr[dst + 1];
    float acc[8];
    #pragma unroll
    for (int j = 0; j < 8; j++) acc[j] = 0.f;

    for (int p = p0; p < p1; p++) {
        float al = __ldg(&g_alpha[(size_t)p * H + hh]);
        uint4 v = *(const uint4*)(g_hh + (size_t)g_csrc[p] * HC + c8);
        float2 f0 = __half22float2(*(__half2*)&v.x);
        float2 f1 = __half22float2(*(__half2*)&v.y);
        float2 f2 = __half22float2(*(__half2*)&v.z);
        float2 f3 = __half22float2(*(__half2*)&v.w);
        acc[0] += al * f0.x; acc[1] += al * f0.y;
        acc[2] += al * f1.x; acc[3] += al * f1.y;
        acc[4] += al * f2.x; acc[5] += al * f2.y;
        acc[6] += al * f3.x; acc[7] += al * f3.y;
    }
    float4 bA = *(const float4*)&b1[c8];
    float4 bB = *(const float4*)&b1[c8 + 4];
    float v0 = fmaxf(acc[0] + bA.x, 0.f), v1 = fmaxf(acc[1] + bA.y, 0.f);
    float v2 = fmaxf(acc[2] + bA.z, 0.f), v3 = fmaxf(acc[3] + bA.w, 0.f);
    float v4 = fmaxf(acc[4] + bB.x, 0.f), v5 = fmaxf(acc[5] + bB.y, 0.f);
    float v6 = fmaxf(acc[6] + bB.z, 0.f), v7 = fmaxf(acc[7] + bB.w, 0.f);
    __half2 o0 = __floats2half2_rn(v0, v1);
    __half2 o1 = __floats2half2_rn(v2, v3);
    __half2 o2 = __floats2half2_rn(v4, v5);
    __half2 o3 = __floats2half2_rn(v6, v7);
    uint4 ov = make_uint4(*(uint32_t*)&o0, *(uint32_t*)&o1, *(uint32_t*)&o2, *(uint32_t*)&o3);
    *(uint4*)(g_ah + (size_t)dst * HC + c8) = ov;
}

// ---------------- layer-2 aggregation: out[dst,c] = relu(mean_h(sum alpha*hh) + b2) ----------------
__global__ __launch_bounds__(128)
void k_agg2(const float* __restrict__ b2, float* __restrict__ out)
{
    __shared__ float s0[64], s1[64];
    int dst = blockIdx.x;
    int t   = threadIdx.x;          // 0..127
    int grp = t >> 6;               // 0..1: heads [grp*10, grp*10+10)
    int c2  = (t & 63) * 2;         // col pair
    int h0  = grp * 10;
    int p0 = g_rowptr[dst], p1 = g_rowptr[dst + 1];
    float a0 = 0.f, a1 = 0.f;
    for (int p = p0; p < p1; p++) {
        const __half* hs = g_hh + (size_t)g_csrc[p] * HC;
        const float*  ap = &g_alpha[(size_t)p * H + h0];
        #pragma unroll
        for (int j = 0; j < 10; j++) {
            float al = __ldg(&ap[j]);
            float2 f = __half22float2(*(const __half2*)&hs[(h0 + j) * C + c2]);
            a0 += al * f.x;
            a1 += al * f.y;
        }
    }
    if (grp == 1) { s0[t & 63] = a0; s1[t & 63] = a1; }
    __syncthreads();
    if (grp == 0) {
        float v0 = (a0 + s0[t]) * (1.f / (float)H) + b2[c2];
        float v1 = (a1 + s1[t]) * (1.f / (float)H) + b2[c2 + 1];
        *(float2*)&out[dst * C + c2] = make_float2(fmaxf(v0, 0.f), fmaxf(v1, 0.f));
    }
}

// ---------------- launch ----------------
extern "C" void kernel_launch(void* const* d_in, const int* in_sizes, int n_in,
                              void* d_out, int out_size)
{
    const float* x   = (const float*)d_in[0];
    const int*   ei  = (const int*)d_in[1];
    const float* W1  = (const float*)d_in[2];
    const float* as1 = (const float*)d_in[3];
    const float* ad1 = (const float*)d_in[4];
    const float* b1  = (const float*)d_in[5];
    const float* W2  = (const float*)d_in[6];
    const float* as2 = (const float*)d_in[7];
    const float* ad2 = (const float*)d_in[8];
    const float* b2  = (const float*)d_in[9];
    float* out = (float*)d_out;

    cudaFuncSetAttribute(k_hgemm, cudaFuncAttributeMaxDynamicSharedMemorySize, GSMEM);

    dim3 gg(HC / 256, M_PAD / 128);                 // (10, 79)
    int att_blocks = (N_NODES * H * 32 + 255) / 256;
    int sm_blocks  = (N_NODES * H + 255) / 256;
    dim3 wsb(32, 8);

    // ----- layer 1 (k_hgemm at launch #4 so ncu's fixed capture hits it) -----
    int a1blocks = (N_NODES * (K1_PAD / 4) + 255) / 256;
    k_acvt<<<a1blocks, 256>>>(x, G_IN, K1_PAD);                      // 1
    k_wsplit<<<dim3(K1_PAD / 32, HC / 32), wsb>>>(W1, G_IN, K1_PAD); // 2
    k_detect<<<1, 256>>>(ei);                                        // 3
    k_hgemm<<<gg, 256, GSMEM>>>(K1_PAD);                             // 4
    // edge normalization + CSR build
    k_norm  <<<(N_EDGES + 255) / 256, 256>>>(ei);
    k_zero_deg<<<(N_NODES + 255) / 256, 256>>>();
    k_count  <<<(EE + 255) / 256, 256>>>();
    k_scan   <<<1, 1024>>>();
    k_scatter<<<(EE + 255) / 256, 256>>>();
    // layer-1 edge phase (agg1 writes fp16 g_ah = layer-2 GEMM input directly)
    k_att<<<att_blocks, 256>>>(as1, ad1);
    k_softmax<<<sm_blocks, 256>>>();
    k_agg1<<<N_NODES, 320>>>(b1);

    // ----- layer 2 -----
    k_wsplit<<<dim3(HC / 32, HC / 32), wsb>>>(W2, HC, HC);
    k_hgemm<<<gg, 256, GSMEM>>>(HC);
    k_att<<<att_blocks, 256>>>(as2, ad2);
    k_softmax<<<sm_blocks, 256>>>();
    k_agg2<<<N_NODES, 128>>>(b2, out);
}

// round 11
// speedup vs baseline: 6.5474x; 1.0902x over previous
#include <cuda_runtime.h>
#include <cuda_fp16.h>
#include <cstdint>

// ---------------- problem constants ----------------
#define N_NODES 10000
#define M_PAD   10112            // 79 * 128
#define N_EDGES 100000
#define EE      110000           // edges + self loops
#define G_IN    2000
#define K1_PAD  2048
#define H       20
#define C       128
#define HC      2560             // H * C
#define NEG_SLOPE 0.2f

// ---------------- scratch (device globals; no allocations) ----------------
__device__ __half g_hh[(size_t)N_NODES * HC];    // fp16 GEMM output (for aggregations)
__device__ float  g_asrc[N_NODES * H];
__device__ float  g_adst[N_NODES * H];
__device__ float  g_alpha[(size_t)EE * H];       // unnormalized exp
__device__ float  g_inv[N_NODES * H];            // 1/sum per (dst, head)
__device__ int    g_rowptr[N_NODES + 1];
__device__ int    g_deg[N_NODES];
__device__ int    g_fill[N_NODES];
__device__ int    g_csrc[EE];
__device__ int    g_is64;
__device__ int    g_esrc[N_EDGES];
__device__ int    g_edst[N_EDGES];
// fp16 GEMM operands: A [m][kpad], W^T [n][kpad]
__device__ __half g_ah[(size_t)M_PAD * HC];
__device__ __half g_wt[(size_t)HC * HC];

// ---------------- helpers ----------------
__device__ __forceinline__ uint32_t smem_u32(const void* p) {
    uint32_t a;
    asm("{ .reg .u64 t; cvta.to.shared.u64 t, %1; cvt.u32.u64 %0, t; }" : "=r"(a) : "l"(p));
    return a;
}
#define SWZ(off) ((off) ^ (((off) >> 3) & 0x70))

__device__ __forceinline__ void cp16(uint32_t dst, const void* src) {
    asm volatile("cp.async.cg.shared.global [%0], [%1], 16;" :: "r"(dst), "l"(src) : "memory");
}
__device__ __forceinline__ void cp_commit() {
    asm volatile("cp.async.commit_group;" ::: "memory");
}
template <int X> __device__ __forceinline__ void cp_wait() {
    asm volatile("cp.async.wait_group %0;" :: "n"(X) : "memory");
}
#define LDSM4(r0, r1, r2, r3, addr) \
    asm volatile("ldmatrix.sync.aligned.m8n8.x4.shared.b16 {%0,%1,%2,%3}, [%4];" \
        : "=r"(r0), "=r"(r1), "=r"(r2), "=r"(r3) : "r"(addr))
#define MMA(c, a, b) \
    asm volatile("mma.sync.aligned.m16n8k16.row.col.f32.f16.f16.f32 " \
        "{%0,%1,%2,%3}, {%4,%5,%6,%7}, {%8,%9}, {%0,%1,%2,%3};" \
        : "+f"((c)[0]), "+f"((c)[1]), "+f"((c)[2]), "+f"((c)[3]) \
        : "r"((a)[0]), "r"((a)[1]), "r"((a)[2]), "r"((a)[3]), "r"((b)[0]), "r"((b)[1]))

// ---------------- edge dtype detection + normalization ----------------
__global__ void k_detect(const int* __restrict__ ei32) {
    __shared__ int any;
    if (threadIdx.x == 0) any = 0;
    __syncthreads();
    if (ei32[2 * threadIdx.x + 1] != 0) atomicOr(&any, 1);
    __syncthreads();
    if (threadIdx.x == 0) g_is64 = (any == 0) ? 1 : 0;
}
__global__ void k_norm(const int* __restrict__ ei32) {
    int e = blockIdx.x * blockDim.x + threadIdx.x;
    if (e >= N_EDGES) return;
    if (g_is64) { g_esrc[e] = ei32[2 * e]; g_edst[e] = ei32[2 * N_EDGES + 2 * e]; }
    else        { g_esrc[e] = ei32[e];     g_edst[e] = ei32[N_EDGES + e]; }
}

// ---------------- CSR build ----------------
__global__ void k_zero_deg() {
    int i = blockIdx.x * blockDim.x + threadIdx.x;
    if (i < N_NODES) g_deg[i] = 0;
}
__global__ void k_count() {
    int e = blockIdx.x * blockDim.x + threadIdx.x;
    if (e >= EE) return;
    int dst = (e < N_EDGES) ? g_edst[e] : (e - N_EDGES);
    atomicAdd(&g_deg[dst], 1);
}
__global__ void k_scan() {
    __shared__ int part[1024];
    int t = threadIdx.x;
    const int CH = (N_NODES + 1023) / 1024;
    int base = t * CH, s = 0;
    for (int i = 0; i < CH; i++) { int idx = base + i; if (idx < N_NODES) s += g_deg[idx]; }
    part[t] = s;
    __syncthreads();
    for (int o = 1; o < 1024; o <<= 1) {
        int v = (t >= o) ? part[t - o] : 0;
        __syncthreads(); part[t] += v; __syncthreads();
    }
    int run = (t > 0) ? part[t - 1] : 0;
    for (int i = 0; i < CH; i++) {
        int idx = base + i;
        if (idx < N_NODES) { g_rowptr[idx] = run; g_fill[idx] = run; run += g_deg[idx]; }
    }
    if (t == 1023) g_rowptr[N_NODES] = part[1023];
}
__global__ void k_scatter() {
    int e = blockIdx.x * blockDim.x + threadIdx.x;
    if (e >= EE) return;
    int src, dst;
    if (e < N_EDGES) { src = g_esrc[e]; dst = g_edst[e]; }
    else             { src = e - N_EDGES; dst = src; }
    int pos = atomicAdd(&g_fill[dst], 1);
    g_csrc[pos] = src;
}

// ---------------- layer-1 activation convert: g_ah[m][kpad] = fp16(x[m][k]) ----------------
__global__ void k_acvt(const float* __restrict__ A, int K, int KPAD) {
    int idx = blockIdx.x * blockDim.x + threadIdx.x;
    int rowlen4 = KPAD >> 2;
    if (idx >= N_NODES * rowlen4) return;
    int row = idx / rowlen4;
    int c4  = (idx - row * rowlen4) << 2;
    float v[4];
    #pragma unroll
    for (int j = 0; j < 4; j++) v[j] = (c4 + j < K) ? A[(size_t)row * K + c4 + j] : 0.f;
    uint32_t w0 = (uint32_t)__half_as_ushort(__float2half_rn(v[0]))
                | ((uint32_t)__half_as_ushort(__float2half_rn(v[1])) << 16);
    uint32_t w1 = (uint32_t)__half_as_ushort(__float2half_rn(v[2]))
                | ((uint32_t)__half_as_ushort(__float2half_rn(v[3])) << 16);
    *(uint2*)&g_ah[(size_t)row * KPAD + c4] = make_uint2(w0, w1);
}

// ---------------- W transpose to fp16: g_wt[n][kpad] = fp16(W[k][n]) ----------------
__global__ void k_wsplit(const float* __restrict__ W, int K, int KPAD) {
    __shared__ float tile[32][33];
    int n0 = blockIdx.y * 32, k0 = blockIdx.x * 32;
    int tx = threadIdx.x, ty = threadIdx.y;     // (32, 8)
    #pragma unroll
    for (int s = 0; s < 32; s += 8) {
        int k = k0 + ty + s;
        tile[ty + s][tx] = (k < K) ? W[(size_t)k * HC + n0 + tx] : 0.f;
    }
    __syncthreads();
    #pragma unroll
    for (int s = 0; s < 32; s += 8) {
        int n = n0 + ty + s;
        int k = k0 + tx;
        g_wt[(size_t)n * KPAD + k] = __float2half_rn(tile[tx][ty + s]);
    }
}

// ---------------- fp16 HMMA GEMM + fused attention scores ----------------
// CTA tile 128x256 (= 2 full heads), K staged 64, 4-stage cp.async pipeline,
// warp tile 64x64. Epilogue: fp16 store + a_src/a_dst reduction (k_att fused).
#define STG4   49152              // A 16K | B 32K
#define OFF_B  16384
#define GSMEM  (4 * STG4)         // 192 KB

__global__ __launch_bounds__(256, 1)
void k_hgemm(int kpad, const float* __restrict__ wsrc, const float* __restrict__ wdst)
{
    extern __shared__ char smem[];
    uint32_t sb = smem_u32(smem);
    int tid  = threadIdx.x;
    int lane = tid & 31;
    int wid  = tid >> 5;
    int wr   = wid >> 2;
    int wc   = wid & 3;
    int row0 = blockIdx.y * 128;
    int col0 = blockIdx.x * 256;
    int nkb  = kpad >> 6;

    float acc[4][8][4];
    #pragma unroll
    for (int i = 0; i < 4; i++)
        #pragma unroll
        for (int j = 0; j < 8; j++)
            #pragma unroll
            for (int q = 0; q < 4; q++) acc[i][j][q] = 0.f;

    auto issue = [&](int kb) {
        int kt = kb << 6;
        uint32_t st = sb + (kb & 3) * STG4;
        #pragma unroll
        for (int i = 0; i < 4; i++) {
            int idx = i * 256 + tid;
            int r = idx >> 3, c = idx & 7;
            uint32_t off = SWZ((uint32_t)(r * 128 + c * 16));
            cp16(st + off, g_ah + (size_t)(row0 + r) * kpad + kt + c * 8);
        }
        #pragma unroll
        for (int i = 0; i < 8; i++) {
            int idx = i * 256 + tid;
            int r = idx >> 3, c = idx & 7;
            uint32_t off = SWZ((uint32_t)(r * 128 + c * 16));
            cp16(st + OFF_B + off, g_wt + (size_t)(col0 + r) * kpad + kt + c * 8);
        }
    };

    issue(0); cp_commit();
    if (nkb > 1) issue(1);
    cp_commit();
    if (nkb > 2) issue(2);
    cp_commit();

    for (int kb = 0; kb < nkb; kb++) {
        cp_wait<2>();
        __syncthreads();
        if (kb + 3 < nkb) issue(kb + 3);
        cp_commit();

        uint32_t tb = sb + (kb & 3) * STG4;
        #pragma unroll
        for (int k16 = 0; k16 < 4; k16++) {
            uint32_t ah[4][4];
            int arow = wr * 64 + (lane & 15);
            uint32_t acol = (uint32_t)(k16 * 32 + (lane >> 4) * 16);
            #pragma unroll
            for (int mt = 0; mt < 4; mt++) {
                uint32_t off = SWZ((uint32_t)((arow + mt * 16) * 128) + acol);
                LDSM4(ah[mt][0], ah[mt][1], ah[mt][2], ah[mt][3], tb + off);
            }
            int mi = lane >> 3;
            int brow = wc * 64 + ((mi >> 1) << 3) + (lane & 7);
            uint32_t bcol = (uint32_t)(k16 * 32 + (mi & 1) * 16);
            #pragma unroll
            for (int half = 0; half < 2; half++) {
                uint32_t bh[4][2];
                #pragma unroll
                for (int q = 0; q < 2; q++) {
                    int nt2 = half * 2 + q;
                    uint32_t off = SWZ((uint32_t)((brow + nt2 * 16) * 128) + bcol);
                    LDSM4(bh[q * 2][0], bh[q * 2][1], bh[q * 2 + 1][0], bh[q * 2 + 1][1],
                          tb + OFF_B + off);
                }
                #pragma unroll
                for (int mt = 0; mt < 4; mt++)
                    #pragma unroll
                    for (int ntl = 0; ntl < 4; ntl++)
                        MMA(acc[mt][half * 4 + ntl], ah[mt], bh[ntl]);
            }
        }
    }

    // ---- epilogue 1: fp16 feature store ----
    #pragma unroll
    for (int mt = 0; mt < 4; mt++) {
        int gr = row0 + wr * 64 + mt * 16 + (lane >> 2);
        #pragma unroll
        for (int nt = 0; nt < 8; nt++) {
            int gc = col0 + wc * 64 + nt * 8 + (lane & 3) * 2;
            if (gr < N_NODES)
                *(__half2*)&g_hh[(size_t)gr * HC + gc] =
                    __floats2half2_rn(acc[mt][nt][0], acc[mt][nt][1]);
            if (gr + 8 < N_NODES)
                *(__half2*)&g_hh[(size_t)(gr + 8) * HC + gc] =
                    __floats2half2_rn(acc[mt][nt][2], acc[mt][nt][3]);
        }
    }

    // ---- epilogue 2: fused attention scores (CTA covers heads 2bx, 2bx+1) ----
    __syncthreads();                      // stage smem no longer needed
    float* s_red = (float*)smem;          // [128 rows][2 heads][2 contrib][2 src/dst]
    int hd      = wc >> 1;
    int contrib = wc & 1;
    int hdg     = 2 * blockIdx.x + hd;
    float wS0[8], wS1[8], wD0[8], wD1[8];
    #pragma unroll
    for (int nt = 0; nt < 8; nt++) {
        int cloc = (wc & 1) * 64 + nt * 8 + (lane & 3) * 2;
        wS0[nt] = __ldg(&wsrc[hdg * C + cloc]);
        wS1[nt] = __ldg(&wsrc[hdg * C + cloc + 1]);
        wD0[nt] = __ldg(&wdst[hdg * C + cloc]);
        wD1[nt] = __ldg(&wdst[hdg * C + cloc + 1]);
    }
    #pragma unroll
    for (int mt = 0; mt < 4; mt++) {
        float sa = 0.f, sbv = 0.f, da = 0.f, db = 0.f;
        #pragma unroll
        for (int nt = 0; nt < 8; nt++) {
            sa  += acc[mt][nt][0] * wS0[nt] + acc[mt][nt][1] * wS1[nt];
            sbv += acc[mt][nt][2] * wS0[nt] + acc[mt][nt][3] * wS1[nt];
            da  += acc[mt][nt][0] * wD0[nt] + acc[mt][nt][1] * wD1[nt];
            db  += acc[mt][nt][2] * wD0[nt] + acc[mt][nt][3] * wD1[nt];
        }
        #pragma unroll
        for (int o = 1; o <= 2; o <<= 1) {
            sa  += __shfl_xor_sync(0xffffffffu, sa,  o);
            sbv += __shfl_xor_sync(0xffffffffu, sbv, o);
            da  += __shfl_xor_sync(0xffffffffu, da,  o);
            db  += __shfl_xor_sync(0xffffffffu, db,  o);
        }
        if ((lane & 3) == 0) {
            int rA = wr * 64 + mt * 16 + (lane >> 2);
            int rB = rA + 8;
            s_red[((rA * 2 + hd) * 2 + contrib) * 2 + 0] = sa;
            s_red[((rA * 2 + hd) * 2 + contrib) * 2 + 1] = da;
            s_red[((rB * 2 + hd) * 2 + contrib) * 2 + 0] = sbv;
            s_red[((rB * 2 + hd) * 2 + contrib) * 2 + 1] = db;
        }
    }
    __syncthreads();
    {
        int r = tid >> 1, h2 = tid & 1;
        int gr = row0 + r;
        if (gr < N_NODES) {
            float vs = s_red[((r * 2 + h2) * 2 + 0) * 2 + 0] + s_red[((r * 2 + h2) * 2 + 1) * 2 + 0];
            float vd = s_red[((r * 2 + h2) * 2 + 0) * 2 + 1] + s_red[((r * 2 + h2) * 2 + 1) * 2 + 1];
            g_asrc[gr * H + 2 * blockIdx.x + h2] = vs;
            g_adst[gr * H + 2 * blockIdx.x + h2] = vd;
        }
    }
}

// ---------------- per-(dst,head) softmax: unnormalized exp + 1/sum ----------------
__global__ void k_softmax() {
    int idx = blockIdx.x * blockDim.x + threadIdx.x;
    if (idx >= N_NODES * H) return;
    int dst = idx / H;
    int hh  = idx - dst * H;
    float ad = g_adst[dst * H + hh];
    int p0 = g_rowptr[dst], p1 = g_rowptr[dst + 1];
    float m = -1e30f;
    for (int p = p0; p < p1; p++) {
        int s = g_csrc[p];
        float ev = g_asrc[s * H + hh] + ad;
        ev = (ev > 0.f) ? ev : NEG_SLOPE * ev;
        g_alpha[(size_t)p * H + hh] = ev;
        m = fmaxf(m, ev);
    }
    float sum = 0.f;
    for (int p = p0; p < p1; p++) {
        float ex = __expf(g_alpha[(size_t)p * H + hh] - m);
        g_alpha[(size_t)p * H + hh] = ex;
        sum += ex;
    }
    g_inv[dst * H + hh] = 1.f / sum;
}

// ---------------- layer-1 aggregation: g_ah[dst,:] = fp16(relu(inv*sum ex*hh + b1)) ----------------
__global__ __launch_bounds__(320)
void k_agg1(const float* __restrict__ b1)
{
    int dst = blockIdx.x;
    int t   = threadIdx.x;          // 0..319
    int c8  = t * 8;                // 8 cols per thread (within head t>>4)
    int hh  = t >> 4;
    int p0 = g_rowptr[dst], p1 = g_rowptr[dst + 1];
    float inv = __ldg(&g_inv[dst * H + hh]);
    float acc[8];
    #pragma unroll
    for (int j = 0; j < 8; j++) acc[j] = 0.f;

    int p = p0;
    for (; p + 2 <= p1; p += 2) {
        float al0 = __ldg(&g_alpha[(size_t)p * H + hh]);
        float al1 = __ldg(&g_alpha[(size_t)(p + 1) * H + hh]);
        uint4 v0 = *(const uint4*)(g_hh + (size_t)__ldg(&g_csrc[p]) * HC + c8);
        uint4 v1 = *(const uint4*)(g_hh + (size_t)__ldg(&g_csrc[p + 1]) * HC + c8);
        float2 a0 = __half22float2(*(__half2*)&v0.x), a1 = __half22float2(*(__half2*)&v0.y);
        float2 a2 = __half22float2(*(__half2*)&v0.z), a3 = __half22float2(*(__half2*)&v0.w);
        float2 b0 = __half22float2(*(__half2*)&v1.x), b1h = __half22float2(*(__half2*)&v1.y);
        float2 b2v = __half22float2(*(__half2*)&v1.z), b3 = __half22float2(*(__half2*)&v1.w);
        acc[0] += al0 * a0.x + al1 * b0.x;  acc[1] += al0 * a0.y + al1 * b0.y;
        acc[2] += al0 * a1.x + al1 * b1h.x; acc[3] += al0 * a1.y + al1 * b1h.y;
        acc[4] += al0 * a2.x + al1 * b2v.x; acc[5] += al0 * a2.y + al1 * b2v.y;
        acc[6] += al0 * a3.x + al1 * b3.x;  acc[7] += al0 * a3.y + al1 * b3.y;
    }
    if (p < p1) {
        float al = __ldg(&g_alpha[(size_t)p * H + hh]);
        uint4 v = *(const uint4*)(g_hh + (size_t)__ldg(&g_csrc[p]) * HC + c8);
        float2 f0 = __half22float2(*(__half2*)&v.x), f1 = __half22float2(*(__half2*)&v.y);
        float2 f2 = __half22float2(*(__half2*)&v.z), f3 = __half22float2(*(__half2*)&v.w);
        acc[0] += al * f0.x; acc[1] += al * f0.y;
        acc[2] += al * f1.x; acc[3] += al * f1.y;
        acc[4] += al * f2.x; acc[5] += al * f2.y;
        acc[6] += al * f3.x; acc[7] += al * f3.y;
    }
    float4 bA = *(const float4*)&b1[c8];
    float4 bB = *(const float4*)&b1[c8 + 4];
    float v0 = fmaxf(acc[0] * inv + bA.x, 0.f), v1 = fmaxf(acc[1] * inv + bA.y, 0.f);
    float v2 = fmaxf(acc[2] * inv + bA.z, 0.f), v3 = fmaxf(acc[3] * inv + bA.w, 0.f);
    float v4 = fmaxf(acc[4] * inv + bB.x, 0.f), v5 = fmaxf(acc[5] * inv + bB.y, 0.f);
    float v6 = fmaxf(acc[6] * inv + bB.z, 0.f), v7 = fmaxf(acc[7] * inv + bB.w, 0.f);
    __half2 o0 = __floats2half2_rn(v0, v1);
    __half2 o1 = __floats2half2_rn(v2, v3);
    __half2 o2 = __floats2half2_rn(v4, v5);
    __half2 o3 = __floats2half2_rn(v6, v7);
    uint4 ov = make_uint4(*(uint32_t*)&o0, *(uint32_t*)&o1, *(uint32_t*)&o2, *(uint32_t*)&o3);
    *(uint4*)(g_ah + (size_t)dst * HC + c8) = ov;
}

// ---------------- layer-2 aggregation: out[dst,c] = relu(mean_h(inv_h*sum ex*hh) + b2) ----------------
__global__ __launch_bounds__(128)
void k_agg2(const float* __restrict__ b2, float* __restrict__ out)
{
    __shared__ float s0[64], s1[64];
    int dst = blockIdx.x;
    int t   = threadIdx.x;          // 0..127
    int grp = t >> 6;               // 0..1: heads [grp*10, grp*10+10)
    int c2  = (t & 63) * 2;         // col pair
    int h0  = grp * 10;
    int p0 = g_rowptr[dst], p1 = g_rowptr[dst + 1];
    float invs[10];
    #pragma unroll
    for (int j = 0; j < 10; j++) invs[j] = __ldg(&g_inv[dst * H + h0 + j]);

    float a0 = 0.f, a1 = 0.f;
    int p = p0;
    for (; p + 2 <= p1; p += 2) {
        const __half* hs0 = g_hh + (size_t)__ldg(&g_csrc[p]) * HC;
        const __half* hs1 = g_hh + (size_t)__ldg(&g_csrc[p + 1]) * HC;
        const float*  ap0 = &g_alpha[(size_t)p * H + h0];
        const float*  ap1 = &g_alpha[(size_t)(p + 1) * H + h0];
        #pragma unroll
        for (int j = 0; j < 10; j++) {
            float al0 = __ldg(&ap0[j]) * invs[j];
            float al1 = __ldg(&ap1[j]) * invs[j];
            float2 f0 = __half22float2(*(const __half2*)&hs0[(h0 + j) * C + c2]);
            float2 f1 = __half22float2(*(const __half2*)&hs1[(h0 + j) * C + c2]);
            a0 += al0 * f0.x + al1 * f1.x;
            a1 += al0 * f0.y + al1 * f1.y;
        }
    }
    if (p < p1) {
        const __half* hs = g_hh + (size_t)__ldg(&g_csrc[p]) * HC;
        const float*  ap = &g_alpha[(size_t)p * H + h0];
        #pragma unroll
        for (int j = 0; j < 10; j++) {
            float al = __ldg(&ap[j]) * invs[j];
            float2 f = __half22float2(*(const __half2*)&hs[(h0 + j) * C + c2]);
            a0 += al * f.x;
            a1 += al * f.y;
        }
    }
    if (grp == 1) { s0[t & 63] = a0; s1[t & 63] = a1; }
    __syncthreads();
    if (grp == 0) {
        float v0 = (a0 + s0[t]) * (1.f / (float)H) + b2[c2];
        float v1 = (a1 + s1[t]) * (1.f / (float)H) + b2[c2 + 1];
        *(float2*)&out[dst * C + c2] = make_float2(fmaxf(v0, 0.f), fmaxf(v1, 0.f));
    }
}

// ---------------- launch ----------------
extern "C" void kernel_launch(void* const* d_in, const int* in_sizes, int n_in,
                              void* d_out, int out_size)
{
    const float* x   = (const float*)d_in[0];
    const int*   ei  = (const int*)d_in[1];
    const float* W1  = (const float*)d_in[2];
    const float* as1 = (const float*)d_in[3];
    const float* ad1 = (const float*)d_in[4];
    const float* b1  = (const float*)d_in[5];
    const float* W2  = (const float*)d_in[6];
    const float* as2 = (const float*)d_in[7];
    const float* ad2 = (const float*)d_in[8];
    const float* b2  = (const float*)d_in[9];
    float* out = (float*)d_out;

    cudaFuncSetAttribute(k_hgemm, cudaFuncAttributeMaxDynamicSharedMemorySize, GSMEM);

    dim3 gg(HC / 256, M_PAD / 128);                 // (10, 79)
    int sm_blocks = (N_NODES * H + 255) / 256;
    dim3 wsb(32, 8);

    // ----- layer 1 (k_hgemm at launch #4 so ncu's fixed capture hits it) -----
    int a1blocks = (N_NODES * (K1_PAD / 4) + 255) / 256;
    k_acvt<<<a1blocks, 256>>>(x, G_IN, K1_PAD);                      // 1
    k_wsplit<<<dim3(K1_PAD / 32, HC / 32), wsb>>>(W1, G_IN, K1_PAD); // 2
    k_detect<<<1, 256>>>(ei);                                        // 3
    k_hgemm<<<gg, 256, GSMEM>>>(K1_PAD, as1, ad1);                   // 4 (att fused)
    // edge normalization + CSR build
    k_norm  <<<(N_EDGES + 255) / 256, 256>>>(ei);
    k_zero_deg<<<(N_NODES + 255) / 256, 256>>>();
    k_count  <<<(EE + 255) / 256, 256>>>();
    k_scan   <<<1, 1024>>>();
    k_scatter<<<(EE + 255) / 256, 256>>>();
    // layer-1 edge phase
    k_softmax<<<sm_blocks, 256>>>();
    k_agg1<<<N_NODES, 320>>>(b1);

    // ----- layer 2 -----
    k_wsplit<<<dim3(HC / 32, HC / 32), wsb>>>(W2, HC, HC);
    k_hgemm<<<gg, 256, GSMEM>>>(HC, as2, ad2);
    k_softmax<<<sm_blocks, 256>>>();
    k_agg2<<<N_NODES, 128>>>(b2, out);
}

// round 12
// speedup vs baseline: 6.7295x; 1.0278x over previous
#include <cuda_runtime.h>
#include <cuda_fp16.h>
#include <cstdint>

// ---------------- problem constants ----------------
#define N_NODES 10000
#define M_PAD   10112            // 79 * 128
#define N_EDGES 100000
#define EE      110000           // edges + self loops
#define G_IN    2000
#define K1_PAD  2048
#define H       20
#define C       128
#define HC      2560             // H * C
#define NEG_SLOPE 0.2f

// ---------------- scratch (device globals; no allocations) ----------------
__device__ __half g_hh[(size_t)N_NODES * HC];    // fp16 GEMM output (for aggregations)
__device__ float  g_asrc[N_NODES * H];
__device__ float  g_adst[N_NODES * H];
__device__ float  g_alpha[(size_t)EE * H];       // unnormalized exp
__device__ float  g_inv[N_NODES * H];            // 1/sum per (dst, head)
__device__ int    g_rowptr[N_NODES + 1];
__device__ int    g_deg[N_NODES];
__device__ int    g_fill[N_NODES];
__device__ int    g_csrc[EE];
__device__ int    g_is64;
__device__ int    g_esrc[N_EDGES];
__device__ int    g_edst[N_EDGES];
// fp16 GEMM operands: A [m][kpad], W^T [n][kpad]
__device__ __half g_ah[(size_t)M_PAD * HC];
__device__ __half g_wt[(size_t)HC * HC];

// ---------------- helpers ----------------
__device__ __forceinline__ uint32_t smem_u32(const void* p) {
    uint32_t a;
    asm("{ .reg .u64 t; cvta.to.shared.u64 t, %1; cvt.u32.u64 %0, t; }" : "=r"(a) : "l"(p));
    return a;
}
#define SWZ(off) ((off) ^ (((off) >> 3) & 0x70))

__device__ __forceinline__ void cp16(uint32_t dst, const void* src) {
    asm volatile("cp.async.cg.shared.global [%0], [%1], 16;" :: "r"(dst), "l"(src) : "memory");
}
__device__ __forceinline__ void cp_commit() {
    asm volatile("cp.async.commit_group;" ::: "memory");
}
template <int X> __device__ __forceinline__ void cp_wait() {
    asm volatile("cp.async.wait_group %0;" :: "n"(X) : "memory");
}
#define LDSM4(r0, r1, r2, r3, addr) \
    asm volatile("ldmatrix.sync.aligned.m8n8.x4.shared.b16 {%0,%1,%2,%3}, [%4];" \
        : "=r"(r0), "=r"(r1), "=r"(r2), "=r"(r3) : "r"(addr))
#define MMA(c, a, b) \
    asm volatile("mma.sync.aligned.m16n8k16.row.col.f32.f16.f16.f32 " \
        "{%0,%1,%2,%3}, {%4,%5,%6,%7}, {%8,%9}, {%0,%1,%2,%3};" \
        : "+f"((c)[0]), "+f"((c)[1]), "+f"((c)[2]), "+f"((c)[3]) \
        : "r"((a)[0]), "r"((a)[1]), "r"((a)[2]), "r"((a)[3]), "r"((b)[0]), "r"((b)[1]))

// ---------------- edge dtype detection + normalization ----------------
__global__ void k_detect(const int* __restrict__ ei32) {
    __shared__ int any;
    if (threadIdx.x == 0) any = 0;
    __syncthreads();
    if (ei32[2 * threadIdx.x + 1] != 0) atomicOr(&any, 1);
    __syncthreads();
    if (threadIdx.x == 0) g_is64 = (any == 0) ? 1 : 0;
}
__global__ void k_norm(const int* __restrict__ ei32) {
    int e = blockIdx.x * blockDim.x + threadIdx.x;
    if (e >= N_EDGES) return;
    if (g_is64) { g_esrc[e] = ei32[2 * e]; g_edst[e] = ei32[2 * N_EDGES + 2 * e]; }
    else        { g_esrc[e] = ei32[e];     g_edst[e] = ei32[N_EDGES + e]; }
}

// ---------------- CSR build ----------------
__global__ void k_zero_deg() {
    int i = blockIdx.x * blockDim.x + threadIdx.x;
    if (i < N_NODES) g_deg[i] = 0;
}
__global__ void k_count() {
    int e = blockIdx.x * blockDim.x + threadIdx.x;
    if (e >= EE) return;
    int dst = (e < N_EDGES) ? g_edst[e] : (e - N_EDGES);
    atomicAdd(&g_deg[dst], 1);
}
__global__ void k_scan() {
    __shared__ int part[1024];
    int t = threadIdx.x;
    const int CH = (N_NODES + 1023) / 1024;
    int base = t * CH, s = 0;
    for (int i = 0; i < CH; i++) { int idx = base + i; if (idx < N_NODES) s += g_deg[idx]; }
    part[t] = s;
    __syncthreads();
    for (int o = 1; o < 1024; o <<= 1) {
        int v = (t >= o) ? part[t - o] : 0;
        __syncthreads(); part[t] += v; __syncthreads();
    }
    int run = (t > 0) ? part[t - 1] : 0;
    for (int i = 0; i < CH; i++) {
        int idx = base + i;
        if (idx < N_NODES) { g_rowptr[idx] = run; g_fill[idx] = run; run += g_deg[idx]; }
    }
    if (t == 1023) g_rowptr[N_NODES] = part[1023];
}
__global__ void k_scatter() {
    int e = blockIdx.x * blockDim.x + threadIdx.x;
    if (e >= EE) return;
    int src, dst;
    if (e < N_EDGES) { src = g_esrc[e]; dst = g_edst[e]; }
    else             { src = e - N_EDGES; dst = src; }
    int pos = atomicAdd(&g_fill[dst], 1);
    g_csrc[pos] = src;
}

// ---------------- layer-1 activation convert: g_ah[m][kpad] = fp16(x[m][k]) ----------------
__global__ void k_acvt(const float* __restrict__ A, int K, int KPAD) {
    int idx = blockIdx.x * blockDim.x + threadIdx.x;
    int rowlen4 = KPAD >> 2;
    if (idx >= N_NODES * rowlen4) return;
    int row = idx / rowlen4;
    int c4  = (idx - row * rowlen4) << 2;
    float v[4];
    #pragma unroll
    for (int j = 0; j < 4; j++) v[j] = (c4 + j < K) ? A[(size_t)row * K + c4 + j] : 0.f;
    uint32_t w0 = (uint32_t)__half_as_ushort(__float2half_rn(v[0]))
                | ((uint32_t)__half_as_ushort(__float2half_rn(v[1])) << 16);
    uint32_t w1 = (uint32_t)__half_as_ushort(__float2half_rn(v[2]))
                | ((uint32_t)__half_as_ushort(__float2half_rn(v[3])) << 16);
    *(uint2*)&g_ah[(size_t)row * KPAD + c4] = make_uint2(w0, w1);
}

// ---------------- W transpose to fp16: g_wt[n][kpad] = fp16(W[k][n]) ----------------
__global__ void k_wsplit(const float* __restrict__ W, int K, int KPAD) {
    __shared__ float tile[32][33];
    int n0 = blockIdx.y * 32, k0 = blockIdx.x * 32;
    int tx = threadIdx.x, ty = threadIdx.y;     // (32, 8)
    #pragma unroll
    for (int s = 0; s < 32; s += 8) {
        int k = k0 + ty + s;
        tile[ty + s][tx] = (k < K) ? W[(size_t)k * HC + n0 + tx] : 0.f;
    }
    __syncthreads();
    #pragma unroll
    for (int s = 0; s < 32; s += 8) {
        int n = n0 + ty + s;
        int k = k0 + tx;
        g_wt[(size_t)n * KPAD + k] = __float2half_rn(tile[tx][ty + s]);
    }
}

// ---------------- fp16 HMMA GEMM + fused attention scores ----------------
// CTA tile 128x128 (= 1 head), warp tile 64x32, K staged 64,
// 3-stage cp.async pipeline, 2 CTAs/SM. Epilogue: fp16 store + att reduction.
#define STG3   32768              // A 16K | B 16K
#define OFF_B  16384
#define GSMEM  (3 * STG3)         // 96 KB

__global__ __launch_bounds__(256, 2)
void k_hgemm(int kpad, const float* __restrict__ wsrc, const float* __restrict__ wdst)
{
    extern __shared__ char smem[];
    uint32_t sb = smem_u32(smem);
    int tid  = threadIdx.x;
    int lane = tid & 31;
    int wid  = tid >> 5;
    int wr   = wid >> 2;            // 0..1  (64-row slabs)
    int wc   = wid & 3;             // 0..3  (32-col slabs)
    int row0 = blockIdx.y * 128;
    int col0 = blockIdx.x * 128;
    int nkb  = kpad >> 6;

    float acc[4][4][4];
    #pragma unroll
    for (int i = 0; i < 4; i++)
        #pragma unroll
        for (int j = 0; j < 4; j++)
            #pragma unroll
            for (int q = 0; q < 4; q++) acc[i][j][q] = 0.f;

    // ---- stage issue: 8 cp.async per thread (32 KB) ----
    auto issue = [&](int kb) {
        int kt = kb << 6;
        uint32_t st = sb + (kb % 3) * STG3;
        #pragma unroll
        for (int i = 0; i < 4; i++) {                 // A: 128 rows
            int idx = i * 256 + tid;
            int r = idx >> 3, c = idx & 7;
            uint32_t off = SWZ((uint32_t)(r * 128 + c * 16));
            cp16(st + off, g_ah + (size_t)(row0 + r) * kpad + kt + c * 8);
        }
        #pragma unroll
        for (int i = 0; i < 4; i++) {                 // B: 128 rows
            int idx = i * 256 + tid;
            int r = idx >> 3, c = idx & 7;
            uint32_t off = SWZ((uint32_t)(r * 128 + c * 16));
            cp16(st + OFF_B + off, g_wt + (size_t)(col0 + r) * kpad + kt + c * 8);
        }
    };

    issue(0); cp_commit();
    if (nkb > 1) issue(1);
    cp_commit();

    for (int kb = 0; kb < nkb; kb++) {
        cp_wait<1>();
        __syncthreads();
        if (kb + 2 < nkb) issue(kb + 2);
        cp_commit();

        uint32_t tb = sb + (kb % 3) * STG3;
        #pragma unroll
        for (int k16 = 0; k16 < 4; k16++) {
            uint32_t ah[4][4], bh[4][2];
            int arow = wr * 64 + (lane & 15);
            uint32_t acol = (uint32_t)(k16 * 32 + (lane >> 4) * 16);
            #pragma unroll
            for (int mt = 0; mt < 4; mt++) {
                uint32_t off = SWZ((uint32_t)((arow + mt * 16) * 128) + acol);
                LDSM4(ah[mt][0], ah[mt][1], ah[mt][2], ah[mt][3], tb + off);
            }
            int mi = lane >> 3;
            int brow = wc * 32 + ((mi >> 1) << 3) + (lane & 7);
            uint32_t bcol = (uint32_t)(k16 * 32 + (mi & 1) * 16);
            #pragma unroll
            for (int g = 0; g < 2; g++) {
                uint32_t off = SWZ((uint32_t)((brow + g * 16) * 128) + bcol);
                LDSM4(bh[g * 2][0], bh[g * 2][1], bh[g * 2 + 1][0], bh[g * 2 + 1][1],
                      tb + OFF_B + off);
            }
            #pragma unroll
            for (int mt = 0; mt < 4; mt++)
                #pragma unroll
                for (int nt = 0; nt < 4; nt++)
                    MMA(acc[mt][nt], ah[mt], bh[nt]);
        }
    }

    // ---- epilogue 1: fp16 feature store ----
    #pragma unroll
    for (int mt = 0; mt < 4; mt++) {
        int gr = row0 + wr * 64 + mt * 16 + (lane >> 2);
        #pragma unroll
        for (int nt = 0; nt < 4; nt++) {
            int gc = col0 + wc * 32 + nt * 8 + (lane & 3) * 2;
            if (gr < N_NODES)
                *(__half2*)&g_hh[(size_t)gr * HC + gc] =
                    __floats2half2_rn(acc[mt][nt][0], acc[mt][nt][1]);
            if (gr + 8 < N_NODES)
                *(__half2*)&g_hh[(size_t)(gr + 8) * HC + gc] =
                    __floats2half2_rn(acc[mt][nt][2], acc[mt][nt][3]);
        }
    }

    // ---- epilogue 2: fused attention scores (CTA = head blockIdx.x) ----
    __syncthreads();                      // stage smem no longer needed
    float* s_red = (float*)smem;          // [128 rows][4 contrib][2 src/dst]
    int hdg = blockIdx.x;
    float wS0[4], wS1[4], wD0[4], wD1[4];
    #pragma unroll
    for (int nt = 0; nt < 4; nt++) {
        int cloc = wc * 32 + nt * 8 + (lane & 3) * 2;
        wS0[nt] = __ldg(&wsrc[hdg * C + cloc]);
        wS1[nt] = __ldg(&wsrc[hdg * C + cloc + 1]);
        wD0[nt] = __ldg(&wdst[hdg * C + cloc]);
        wD1[nt] = __ldg(&wdst[hdg * C + cloc + 1]);
    }
    #pragma unroll
    for (int mt = 0; mt < 4; mt++) {
        float sa = 0.f, sbv = 0.f, da = 0.f, db = 0.f;
        #pragma unroll
        for (int nt = 0; nt < 4; nt++) {
            sa  += acc[mt][nt][0] * wS0[nt] + acc[mt][nt][1] * wS1[nt];
            sbv += acc[mt][nt][2] * wS0[nt] + acc[mt][nt][3] * wS1[nt];
            da  += acc[mt][nt][0] * wD0[nt] + acc[mt][nt][1] * wD1[nt];
            db  += acc[mt][nt][2] * wD0[nt] + acc[mt][nt][3] * wD1[nt];
        }
        #pragma unroll
        for (int o = 1; o <= 2; o <<= 1) {
            sa  += __shfl_xor_sync(0xffffffffu, sa,  o);
            sbv += __shfl_xor_sync(0xffffffffu, sbv, o);
            da  += __shfl_xor_sync(0xffffffffu, da,  o);
            db  += __shfl_xor_sync(0xffffffffu, db,  o);
        }
        if ((lane & 3) == 0) {
            int rA = wr * 64 + mt * 16 + (lane >> 2);
            int rB = rA + 8;
            s_red[(rA * 4 + wc) * 2 + 0] = sa;
            s_red[(rA * 4 + wc) * 2 + 1] = da;
            s_red[(rB * 4 + wc) * 2 + 0] = sbv;
            s_red[(rB * 4 + wc) * 2 + 1] = db;
        }
    }
    __syncthreads();
    if (tid < 128) {
        int gr = row0 + tid;
        if (gr < N_NODES) {
            float vs = s_red[(tid * 4 + 0) * 2] + s_red[(tid * 4 + 1) * 2]
                     + s_red[(tid * 4 + 2) * 2] + s_red[(tid * 4 + 3) * 2];
            float vd = s_red[(tid * 4 + 0) * 2 + 1] + s_red[(tid * 4 + 1) * 2 + 1]
                     + s_red[(tid * 4 + 2) * 2 + 1] + s_red[(tid * 4 + 3) * 2 + 1];
            g_asrc[gr * H + hdg] = vs;
            g_adst[gr * H + hdg] = vd;
        }
    }
}

// ---------------- per-(dst,head) softmax: unnormalized exp + 1/sum ----------------
__global__ void k_softmax() {
    int idx = blockIdx.x * blockDim.x + threadIdx.x;
    if (idx >= N_NODES * H) return;
    int dst = idx / H;
    int hh  = idx - dst * H;
    float ad = g_adst[dst * H + hh];
    int p0 = g_rowptr[dst], p1 = g_rowptr[dst + 1];
    float m = -1e30f;
    for (int p = p0; p < p1; p++) {
        int s = g_csrc[p];
        float ev = g_asrc[s * H + hh] + ad;
        ev = (ev > 0.f) ? ev : NEG_SLOPE * ev;
        g_alpha[(size_t)p * H + hh] = ev;
        m = fmaxf(m, ev);
    }
    float sum = 0.f;
    for (int p = p0; p < p1; p++) {
        float ex = __expf(g_alpha[(size_t)p * H + hh] - m);
        g_alpha[(size_t)p * H + hh] = ex;
        sum += ex;
    }
    g_inv[dst * H + hh] = 1.f / sum;
}

// ---------------- layer-1 aggregation: g_ah[dst,:] = fp16(relu(inv*sum ex*hh + b1)) ----------------
__global__ __launch_bounds__(320)
void k_agg1(const float* __restrict__ b1)
{
    int dst = blockIdx.x;
    int t   = threadIdx.x;          // 0..319
    int c8  = t * 8;                // 8 cols per thread (within head t>>4)
    int hh  = t >> 4;
    int p0 = g_rowptr[dst], p1 = g_rowptr[dst + 1];
    float inv = __ldg(&g_inv[dst * H + hh]);
    float acc[8];
    #pragma unroll
    for (int j = 0; j < 8; j++) acc[j] = 0.f;

    int p = p0;
    for (; p + 2 <= p1; p += 2) {
        float al0 = __ldg(&g_alpha[(size_t)p * H + hh]);
        float al1 = __ldg(&g_alpha[(size_t)(p + 1) * H + hh]);
        uint4 v0 = *(const uint4*)(g_hh + (size_t)__ldg(&g_csrc[p]) * HC + c8);
        uint4 v1 = *(const uint4*)(g_hh + (size_t)__ldg(&g_csrc[p + 1]) * HC + c8);
        float2 a0 = __half22float2(*(__half2*)&v0.x), a1 = __half22float2(*(__half2*)&v0.y);
        float2 a2 = __half22float2(*(__half2*)&v0.z), a3 = __half22float2(*(__half2*)&v0.w);
        float2 b0 = __half22float2(*(__half2*)&v1.x), b1h = __half22float2(*(__half2*)&v1.y);
        float2 b2v = __half22float2(*(__half2*)&v1.z), b3 = __half22float2(*(__half2*)&v1.w);
        acc[0] += al0 * a0.x + al1 * b0.x;  acc[1] += al0 * a0.y + al1 * b0.y;
        acc[2] += al0 * a1.x + al1 * b1h.x; acc[3] += al0 * a1.y + al1 * b1h.y;
        acc[4] += al0 * a2.x + al1 * b2v.x; acc[5] += al0 * a2.y + al1 * b2v.y;
        acc[6] += al0 * a3.x + al1 * b3.x;  acc[7] += al0 * a3.y + al1 * b3.y;
    }
    if (p < p1) {
        float al = __ldg(&g_alpha[(size_t)p * H + hh]);
        uint4 v = *(const uint4*)(g_hh + (size_t)__ldg(&g_csrc[p]) * HC + c8);
        float2 f0 = __half22float2(*(__half2*)&v.x), f1 = __half22float2(*(__half2*)&v.y);
        float2 f2 = __half22float2(*(__half2*)&v.z), f3 = __half22float2(*(__half2*)&v.w);
        acc[0] += al * f0.x; acc[1] += al * f0.y;
        acc[2] += al * f1.x; acc[3] += al * f1.y;
        acc[4] += al * f2.x; acc[5] += al * f2.y;
        acc[6] += al * f3.x; acc[7] += al * f3.y;
    }
    float4 bA = *(const float4*)&b1[c8];
    float4 bB = *(const float4*)&b1[c8 + 4];
    float v0 = fmaxf(acc[0] * inv + bA.x, 0.f), v1 = fmaxf(acc[1] * inv + bA.y, 0.f);
    float v2 = fmaxf(acc[2] * inv + bA.z, 0.f), v3 = fmaxf(acc[3] * inv + bA.w, 0.f);
    float v4 = fmaxf(acc[4] * inv + bB.x, 0.f), v5 = fmaxf(acc[5] * inv + bB.y, 0.f);
    float v6 = fmaxf(acc[6] * inv + bB.z, 0.f), v7 = fmaxf(acc[7] * inv + bB.w, 0.f);
    __half2 o0 = __floats2half2_rn(v0, v1);
    __half2 o1 = __floats2half2_rn(v2, v3);
    __half2 o2 = __floats2half2_rn(v4, v5);
    __half2 o3 = __floats2half2_rn(v6, v7);
    uint4 ov = make_uint4(*(uint32_t*)&o0, *(uint32_t*)&o1, *(uint32_t*)&o2, *(uint32_t*)&o3);
    *(uint4*)(g_ah + (size_t)dst * HC + c8) = ov;
}

// ---------------- layer-2 aggregation: out[dst,c] = relu(mean_h(inv_h*sum ex*hh) + b2) ----------------
__global__ __launch_bounds__(128)
void k_agg2(const float* __restrict__ b2, float* __restrict__ out)
{
    __shared__ float s0[64], s1[64];
    int dst = blockIdx.x;
    int t   = threadIdx.x;          // 0..127
    int grp = t >> 6;               // 0..1: heads [grp*10, grp*10+10)
    int c2  = (t & 63) * 2;         // col pair
    int h0  = grp * 10;
    int p0 = g_rowptr[dst], p1 = g_rowptr[dst + 1];
    float invs[10];
    #pragma unroll
    for (int j = 0; j < 10; j++) invs[j] = __ldg(&g_inv[dst * H + h0 + j]);

    float a0 = 0.f, a1 = 0.f;
    int p = p0;
    for (; p + 2 <= p1; p += 2) {
        const __half* hs0 = g_hh + (size_t)__ldg(&g_csrc[p]) * HC;
        const __half* hs1 = g_hh + (size_t)__ldg(&g_csrc[p + 1]) * HC;
        const float*  ap0 = &g_alpha[(size_t)p * H + h0];
        const float*  ap1 = &g_alpha[(size_t)(p + 1) * H + h0];
        #pragma unroll
        for (int j = 0; j < 10; j++) {
            float al0 = __ldg(&ap0[j]) * invs[j];
            float al1 = __ldg(&ap1[j]) * invs[j];
            float2 f0 = __half22float2(*(const __half2*)&hs0[(h0 + j) * C + c2]);
            float2 f1 = __half22float2(*(const __half2*)&hs1[(h0 + j) * C + c2]);
            a0 += al0 * f0.x + al1 * f1.x;
            a1 += al0 * f0.y + al1 * f1.y;
        }
    }
    if (p < p1) {
        const __half* hs = g_hh + (size_t)__ldg(&g_csrc[p]) * HC;
        const float*  ap = &g_alpha[(size_t)p * H + h0];
        #pragma unroll
        for (int j = 0; j < 10; j++) {
            float al = __ldg(&ap[j]) * invs[j];
            float2 f = __half22float2(*(const __half2*)&hs[(h0 + j) * C + c2]);
            a0 += al * f.x;
            a1 += al * f.y;
        }
    }
    if (grp == 1) { s0[t & 63] = a0; s1[t & 63] = a1; }
    __syncthreads();
    if (grp == 0) {
        float v0 = (a0 + s0[t]) * (1.f / (float)H) + b2[c2];
        float v1 = (a1 + s1[t]) * (1.f / (float)H) + b2[c2 + 1];
        *(float2*)&out[dst * C + c2] = make_float2(fmaxf(v0, 0.f), fmaxf(v1, 0.f));
    }
}

// ---------------- launch ----------------
extern "C" void kernel_launch(void* const* d_in, const int* in_sizes, int n_in,
                              void* d_out, int out_size)
{
    const float* x   = (const float*)d_in[0];
    const int*   ei  = (const int*)d_in[1];
    const float* W1  = (const float*)d_in[2];
    const float* as1 = (const float*)d_in[3];
    const float* ad1 = (const float*)d_in[4];
    const float* b1  = (const float*)d_in[5];
    const float* W2  = (const float*)d_in[6];
    const float* as2 = (const float*)d_in[7];
    const float* ad2 = (const float*)d_in[8];
    const float* b2  = (const float*)d_in[9];
    float* out = (float*)d_out;

    cudaFuncSetAttribute(k_hgemm, cudaFuncAttributeMaxDynamicSharedMemorySize, GSMEM);

    dim3 gg(HC / 128, M_PAD / 128);                 // (20, 79)
    int sm_blocks = (N_NODES * H + 255) / 256;
    dim3 wsb(32, 8);

    // ----- layer 1 (k_hgemm at launch #4 so ncu's fixed capture hits it) -----
    int a1blocks = (N_NODES * (K1_PAD / 4) + 255) / 256;
    k_acvt<<<a1blocks, 256>>>(x, G_IN, K1_PAD);                      // 1
    k_wsplit<<<dim3(K1_PAD / 32, HC / 32), wsb>>>(W1, G_IN, K1_PAD); // 2
    k_detect<<<1, 256>>>(ei);                                        // 3
    k_hgemm<<<gg, 256, GSMEM>>>(K1_PAD, as1, ad1);                   // 4 (att fused)
    // edge normalization + CSR build
    k_norm  <<<(N_EDGES + 255) / 256, 256>>>(ei);
    k_zero_deg<<<(N_NODES + 255) / 256, 256>>>();
    k_count  <<<(EE + 255) / 256, 256>>>();
    k_scan   <<<1, 1024>>>();
    k_scatter<<<(EE + 255) / 256, 256>>>();
    // layer-1 edge phase
    k_softmax<<<sm_blocks, 256>>>();
    k_agg1<<<N_NODES, 320>>>(b1);

    // ----- layer 2 -----
    k_wsplit<<<dim3(HC / 32, HC / 32), wsb>>>(W2, HC, HC);
    k_hgemm<<<gg, 256, GSMEM>>>(HC, as2, ad2);
    k_softmax<<<sm_blocks, 256>>>();
    k_agg2<<<N_NODES, 128>>>(b2, out);
}

// round 13
// speedup vs baseline: 7.0420x; 1.0464x over previous
#include <cuda_runtime.h>
#include <cuda_fp16.h>
#include <cstdint>

// ---------------- problem constants ----------------
#define N_NODES 10000
#define M_PAD   10112            // 79 * 128
#define N_EDGES 100000
#define EE      110000           // edges + self loops
#define G_IN    2000
#define K1_PAD  2048
#define H       20
#define C       128
#define HC      2560             // H * C
#define NEG_SLOPE 0.2f

// ---------------- scratch (device globals; no allocations) ----------------
__device__ __half g_hh[(size_t)N_NODES * HC];    // fp16 GEMM output (for aggregations)
__device__ float  g_asrc[N_NODES * H];
__device__ float  g_adst[N_NODES * H];
__device__ float  g_alpha[(size_t)EE * H];       // unnormalized exp
__device__ float  g_inv[N_NODES * H];            // 1/sum per (dst, head)
__device__ int    g_rowptr[N_NODES + 1];
__device__ int    g_deg[N_NODES];
__device__ int    g_fill[N_NODES];
__device__ int    g_csrc[EE];
__device__ int    g_is64;
__device__ int    g_esrc[N_EDGES];
__device__ int    g_edst[N_EDGES];
// fp16 GEMM operands: A [m][kpad], W^T [n][kpad]
__device__ __half g_ah[(size_t)M_PAD * HC];
__device__ __half g_wt[(size_t)HC * HC];

// ---------------- helpers ----------------
__device__ __forceinline__ uint32_t smem_u32(const void* p) {
    uint32_t a;
    asm("{ .reg .u64 t; cvta.to.shared.u64 t, %1; cvt.u32.u64 %0, t; }" : "=r"(a) : "l"(p));
    return a;
}
#define SWZ(off) ((off) ^ (((off) >> 3) & 0x70))

__device__ __forceinline__ void cp16(uint32_t dst, const void* src) {
    asm volatile("cp.async.cg.shared.global [%0], [%1], 16;" :: "r"(dst), "l"(src) : "memory");
}
__device__ __forceinline__ void cp_commit() {
    asm volatile("cp.async.commit_group;" ::: "memory");
}
template <int X> __device__ __forceinline__ void cp_wait() {
    asm volatile("cp.async.wait_group %0;" :: "n"(X) : "memory");
}
#define LDSM4(r0, r1, r2, r3, addr) \
    asm volatile("ldmatrix.sync.aligned.m8n8.x4.shared.b16 {%0,%1,%2,%3}, [%4];" \
        : "=r"(r0), "=r"(r1), "=r"(r2), "=r"(r3) : "r"(addr))
#define MMA(c, a, b) \
    asm volatile("mma.sync.aligned.m16n8k16.row.col.f32.f16.f16.f32 " \
        "{%0,%1,%2,%3}, {%4,%5,%6,%7}, {%8,%9}, {%0,%1,%2,%3};" \
        : "+f"((c)[0]), "+f"((c)[1]), "+f"((c)[2]), "+f"((c)[3]) \
        : "r"((a)[0]), "r"((a)[1]), "r"((a)[2]), "r"((a)[3]), "r"((b)[0]), "r"((b)[1]))

// ---------------- edge dtype detection + normalization ----------------
__global__ void k_detect(const int* __restrict__ ei32) {
    __shared__ int any;
    if (threadIdx.x == 0) any = 0;
    __syncthreads();
    if (ei32[2 * threadIdx.x + 1] != 0) atomicOr(&any, 1);
    __syncthreads();
    if (threadIdx.x == 0) g_is64 = (any == 0) ? 1 : 0;
}
__global__ void k_norm(const int* __restrict__ ei32) {
    int e = blockIdx.x * blockDim.x + threadIdx.x;
    if (e >= N_EDGES) return;
    if (g_is64) { g_esrc[e] = ei32[2 * e]; g_edst[e] = ei32[2 * N_EDGES + 2 * e]; }
    else        { g_esrc[e] = ei32[e];     g_edst[e] = ei32[N_EDGES + e]; }
}

// ---------------- CSR build ----------------
__global__ void k_zero_deg() {
    int i = blockIdx.x * blockDim.x + threadIdx.x;
    if (i < N_NODES) g_deg[i] = 0;
}
__global__ void k_count() {
    int e = blockIdx.x * blockDim.x + threadIdx.x;
    if (e >= EE) return;
    int dst = (e < N_EDGES) ? g_edst[e] : (e - N_EDGES);
    atomicAdd(&g_deg[dst], 1);
}
__global__ void k_scan() {
    __shared__ int part[1024];
    int t = threadIdx.x;
    const int CH = (N_NODES + 1023) / 1024;
    int base = t * CH, s = 0;
    for (int i = 0; i < CH; i++) { int idx = base + i; if (idx < N_NODES) s += g_deg[idx]; }
    part[t] = s;
    __syncthreads();
    for (int o = 1; o < 1024; o <<= 1) {
        int v = (t >= o) ? part[t - o] : 0;
        __syncthreads(); part[t] += v; __syncthreads();
    }
    int run = (t > 0) ? part[t - 1] : 0;
    for (int i = 0; i < CH; i++) {
        int idx = base + i;
        if (idx < N_NODES) { g_rowptr[idx] = run; g_fill[idx] = run; run += g_deg[idx]; }
    }
    if (t == 1023) g_rowptr[N_NODES] = part[1023];
}
__global__ void k_scatter() {
    int e = blockIdx.x * blockDim.x + threadIdx.x;
    if (e >= EE) return;
    int src, dst;
    if (e < N_EDGES) { src = g_esrc[e]; dst = g_edst[e]; }
    else             { src = e - N_EDGES; dst = src; }
    int pos = atomicAdd(&g_fill[dst], 1);
    g_csrc[pos] = src;
}

// ---------------- layer-1 activation convert: g_ah[m][kpad] = fp16(x[m][k]) ----------------
__global__ void k_acvt(const float* __restrict__ A, int K, int KPAD) {
    int idx = blockIdx.x * blockDim.x + threadIdx.x;
    int rowlen4 = KPAD >> 2;
    if (idx >= N_NODES * rowlen4) return;
    int row = idx / rowlen4;
    int c4  = (idx - row * rowlen4) << 2;
    float v[4];
    #pragma unroll
    for (int j = 0; j < 4; j++) v[j] = (c4 + j < K) ? A[(size_t)row * K + c4 + j] : 0.f;
    uint32_t w0 = (uint32_t)__half_as_ushort(__float2half_rn(v[0]))
                | ((uint32_t)__half_as_ushort(__float2half_rn(v[1])) << 16);
    uint32_t w1 = (uint32_t)__half_as_ushort(__float2half_rn(v[2]))
                | ((uint32_t)__half_as_ushort(__float2half_rn(v[3])) << 16);
    *(uint2*)&g_ah[(size_t)row * KPAD + c4] = make_uint2(w0, w1);
}

// ---------------- W transpose to fp16: g_wt[n][kpad] = fp16(W[k][n]) ----------------
__global__ void k_wsplit(const float* __restrict__ W, int K, int KPAD) {
    __shared__ float tile[32][33];
    int n0 = blockIdx.y * 32, k0 = blockIdx.x * 32;
    int tx = threadIdx.x, ty = threadIdx.y;     // (32, 8)
    #pragma unroll
    for (int s = 0; s < 32; s += 8) {
        int k = k0 + ty + s;
        tile[ty + s][tx] = (k < K) ? W[(size_t)k * HC + n0 + tx] : 0.f;
    }
    __syncthreads();
    #pragma unroll
    for (int s = 0; s < 32; s += 8) {
        int n = n0 + ty + s;
        int k = k0 + tx;
        g_wt[(size_t)n * KPAD + k] = __float2half_rn(tile[tx][ty + s]);
    }
}

// ---------------- fp16 HMMA GEMM + fused attention scores ----------------
// CTA tile 128x128 (= 1 head), 4 warps (128 thr), warp tile 64x64,
// K staged 64, 3-stage cp.async pipeline, 2 CTAs/SM.
#define STG3   32768              // A 16K | B 16K
#define OFF_B  16384
#define GSMEM  (3 * STG3)         // 96 KB

__global__ __launch_bounds__(128, 2)
void k_hgemm(int kpad, const float* __restrict__ wsrc, const float* __restrict__ wdst)
{
    extern __shared__ char smem[];
    uint32_t sb = smem_u32(smem);
    int tid  = threadIdx.x;
    int lane = tid & 31;
    int wid  = tid >> 5;            // 0..3
    int wr   = wid >> 1;            // 0..1  (64-row slabs)
    int wc   = wid & 1;             // 0..1  (64-col slabs)
    int row0 = blockIdx.y * 128;
    int col0 = blockIdx.x * 128;
    int nkb  = kpad >> 6;

    float acc[4][8][4];
    #pragma unroll
    for (int i = 0; i < 4; i++)
        #pragma unroll
        for (int j = 0; j < 8; j++)
            #pragma unroll
            for (int q = 0; q < 4; q++) acc[i][j][q] = 0.f;

    // ---- stage issue: 16 cp.async per thread (32 KB) ----
    auto issue = [&](int kb) {
        int kt = kb << 6;
        uint32_t st = sb + (kb % 3) * STG3;
        #pragma unroll
        for (int i = 0; i < 8; i++) {                 // A: 128 rows
            int idx = i * 128 + tid;
            int r = idx >> 3, c = idx & 7;
            uint32_t off = SWZ((uint32_t)(r * 128 + c * 16));
            cp16(st + off, g_ah + (size_t)(row0 + r) * kpad + kt + c * 8);
        }
        #pragma unroll
        for (int i = 0; i < 8; i++) {                 // B: 128 rows
            int idx = i * 128 + tid;
            int r = idx >> 3, c = idx & 7;
            uint32_t off = SWZ((uint32_t)(r * 128 + c * 16));
            cp16(st + OFF_B + off, g_wt + (size_t)(col0 + r) * kpad + kt + c * 8);
        }
    };

    issue(0); cp_commit();
    if (nkb > 1) issue(1);
    cp_commit();

    for (int kb = 0; kb < nkb; kb++) {
        cp_wait<1>();
        __syncthreads();
        if (kb + 2 < nkb) issue(kb + 2);
        cp_commit();

        uint32_t tb = sb + (kb % 3) * STG3;
        #pragma unroll
        for (int k16 = 0; k16 < 4; k16++) {
            uint32_t ah[4][4];
            int arow = wr * 64 + (lane & 15);
            uint32_t acol = (uint32_t)(k16 * 32 + (lane >> 4) * 16);
            #pragma unroll
            for (int mt = 0; mt < 4; mt++) {
                uint32_t off = SWZ((uint32_t)((arow + mt * 16) * 128) + acol);
                LDSM4(ah[mt][0], ah[mt][1], ah[mt][2], ah[mt][3], tb + off);
            }
            int mi = lane >> 3;
            int brow = wc * 64 + ((mi >> 1) << 3) + (lane & 7);
            uint32_t bcol = (uint32_t)(k16 * 32 + (mi & 1) * 16);
            #pragma unroll
            for (int half = 0; half < 2; half++) {
                uint32_t bh[4][2];
                #pragma unroll
                for (int q = 0; q < 2; q++) {
                    int nt2 = half * 2 + q;
                    uint32_t off = SWZ((uint32_t)((brow + nt2 * 16) * 128) + bcol);
                    LDSM4(bh[q * 2][0], bh[q * 2][1], bh[q * 2 + 1][0], bh[q * 2 + 1][1],
                          tb + OFF_B + off);
                }
                #pragma unroll
                for (int mt = 0; mt < 4; mt++)
                    #pragma unroll
                    for (int ntl = 0; ntl < 4; ntl++)
                        MMA(acc[mt][half * 4 + ntl], ah[mt], bh[ntl]);
            }
        }
    }

    // ---- epilogue 1: fp16 feature store ----
    #pragma unroll
    for (int mt = 0; mt < 4; mt++) {
        int gr = row0 + wr * 64 + mt * 16 + (lane >> 2);
        #pragma unroll
        for (int nt = 0; nt < 8; nt++) {
            int gc = col0 + wc * 64 + nt * 8 + (lane & 3) * 2;
            if (gr < N_NODES)
                *(__half2*)&g_hh[(size_t)gr * HC + gc] =
                    __floats2half2_rn(acc[mt][nt][0], acc[mt][nt][1]);
            if (gr + 8 < N_NODES)
                *(__half2*)&g_hh[(size_t)(gr + 8) * HC + gc] =
                    __floats2half2_rn(acc[mt][nt][2], acc[mt][nt][3]);
        }
    }

    // ---- epilogue 2: fused attention scores (CTA = head blockIdx.x) ----
    __syncthreads();                      // stage smem no longer needed
    float* s_red = (float*)smem;          // [128 rows][2 contrib][2 src/dst]
    int hdg = blockIdx.x;
    float wS0[8], wS1[8], wD0[8], wD1[8];
    #pragma unroll
    for (int nt = 0; nt < 8; nt++) {
        int cloc = wc * 64 + nt * 8 + (lane & 3) * 2;
        wS0[nt] = __ldg(&wsrc[hdg * C + cloc]);
        wS1[nt] = __ldg(&wsrc[hdg * C + cloc + 1]);
        wD0[nt] = __ldg(&wdst[hdg * C + cloc]);
        wD1[nt] = __ldg(&wdst[hdg * C + cloc + 1]);
    }
    #pragma unroll
    for (int mt = 0; mt < 4; mt++) {
        float sa = 0.f, sbv = 0.f, da = 0.f, db = 0.f;
        #pragma unroll
        for (int nt = 0; nt < 8; nt++) {
            sa  += acc[mt][nt][0] * wS0[nt] + acc[mt][nt][1] * wS1[nt];
            sbv += acc[mt][nt][2] * wS0[nt] + acc[mt][nt][3] * wS1[nt];
            da  += acc[mt][nt][0] * wD0[nt] + acc[mt][nt][1] * wD1[nt];
            db  += acc[mt][nt][2] * wD0[nt] + acc[mt][nt][3] * wD1[nt];
        }
        #pragma unroll
        for (int o = 1; o <= 2; o <<= 1) {
            sa  += __shfl_xor_sync(0xffffffffu, sa,  o);
            sbv += __shfl_xor_sync(0xffffffffu, sbv, o);
            da  += __shfl_xor_sync(0xffffffffu, da,  o);
            db  += __shfl_xor_sync(0xffffffffu, db,  o);
        }
        if ((lane & 3) == 0) {
            int rA = wr * 64 + mt * 16 + (lane >> 2);
            int rB = rA + 8;
            s_red[(rA * 2 + wc) * 2 + 0] = sa;
            s_red[(rA * 2 + wc) * 2 + 1] = da;
            s_red[(rB * 2 + wc) * 2 + 0] = sbv;
            s_red[(rB * 2 + wc) * 2 + 1] = db;
        }
    }
    __syncthreads();
    {
        int gr = row0 + tid;
        if (gr < N_NODES) {
            float vs = s_red[(tid * 2 + 0) * 2 + 0] + s_red[(tid * 2 + 1) * 2 + 0];
            float vd = s_red[(tid * 2 + 0) * 2 + 1] + s_red[(tid * 2 + 1) * 2 + 1];
            g_asrc[gr * H + hdg] = vs;
            g_adst[gr * H + hdg] = vd;
        }
    }
}

// ---------------- per-(dst,head) softmax: unnormalized exp + 1/sum ----------------
__global__ void k_softmax() {
    int idx = blockIdx.x * blockDim.x + threadIdx.x;
    if (idx >= N_NODES * H) return;
    int dst = idx / H;
    int hh  = idx - dst * H;
    float ad = g_adst[dst * H + hh];
    int p0 = g_rowptr[dst], p1 = g_rowptr[dst + 1];
    float m = -1e30f;
    for (int p = p0; p < p1; p++) {
        int s = g_csrc[p];
        float ev = g_asrc[s * H + hh] + ad;
        ev = (ev > 0.f) ? ev : NEG_SLOPE * ev;
        g_alpha[(size_t)p * H + hh] = ev;
        m = fmaxf(m, ev);
    }
    float sum = 0.f;
    for (int p = p0; p < p1; p++) {
        float ex = __expf(g_alpha[(size_t)p * H + hh] - m);
        g_alpha[(size_t)p * H + hh] = ex;
        sum += ex;
    }
    g_inv[dst * H + hh] = 1.f / sum;
}

// ---------------- layer-1 aggregation: g_ah[dst,:] = fp16(relu(inv*sum ex*hh + b1)) ----------------
__global__ __launch_bounds__(320)
void k_agg1(const float* __restrict__ b1)
{
    int dst = blockIdx.x;
    int t   = threadIdx.x;          // 0..319
    int c8  = t * 8;                // 8 cols per thread (within head t>>4)
    int hh  = t >> 4;
    int p0 = g_rowptr[dst], p1 = g_rowptr[dst + 1];
    float inv = __ldg(&g_inv[dst * H + hh]);
    float acc[8];
    #pragma unroll
    for (int j = 0; j < 8; j++) acc[j] = 0.f;

    int p = p0;
    for (; p + 2 <= p1; p += 2) {
        float al0 = __ldg(&g_alpha[(size_t)p * H + hh]);
        float al1 = __ldg(&g_alpha[(size_t)(p + 1) * H + hh]);
        uint4 v0 = *(const uint4*)(g_hh + (size_t)__ldg(&g_csrc[p]) * HC + c8);
        uint4 v1 = *(const uint4*)(g_hh + (size_t)__ldg(&g_csrc[p + 1]) * HC + c8);
        float2 a0 = __half22float2(*(__half2*)&v0.x), a1 = __half22float2(*(__half2*)&v0.y);
        float2 a2 = __half22float2(*(__half2*)&v0.z), a3 = __half22float2(*(__half2*)&v0.w);
        float2 b0 = __half22float2(*(__half2*)&v1.x), b1h = __half22float2(*(__half2*)&v1.y);
        float2 b2v = __half22float2(*(__half2*)&v1.z), b3 = __half22float2(*(__half2*)&v1.w);
        acc[0] += al0 * a0.x + al1 * b0.x;  acc[1] += al0 * a0.y + al1 * b0.y;
        acc[2] += al0 * a1.x + al1 * b1h.x; acc[3] += al0 * a1.y + al1 * b1h.y;
        acc[4] += al0 * a2.x + al1 * b2v.x; acc[5] += al0 * a2.y + al1 * b2v.y;
        acc[6] += al0 * a3.x + al1 * b3.x;  acc[7] += al0 * a3.y + al1 * b3.y;
    }
    if (p < p1) {
        float al = __ldg(&g_alpha[(size_t)p * H + hh]);
        uint4 v = *(const uint4*)(g_hh + (size_t)__ldg(&g_csrc[p]) * HC + c8);
        float2 f0 = __half22float2(*(__half2*)&v.x), f1 = __half22float2(*(__half2*)&v.y);
        float2 f2 = __half22float2(*(__half2*)&v.z), f3 = __half22float2(*(__half2*)&v.w);
        acc[0] += al * f0.x; acc[1] += al * f0.y;
        acc[2] += al * f1.x; acc[3] += al * f1.y;
        acc[4] += al * f2.x; acc[5] += al * f2.y;
        acc[6] += al * f3.x; acc[7] += al * f3.y;
    }
    float4 bA = *(const float4*)&b1[c8];
    float4 bB = *(const float4*)&b1[c8 + 4];
    float v0 = fmaxf(acc[0] * inv + bA.x, 0.f), v1 = fmaxf(acc[1] * inv + bA.y, 0.f);
    float v2 = fmaxf(acc[2] * inv + bA.z, 0.f), v3 = fmaxf(acc[3] * inv + bA.w, 0.f);
    float v4 = fmaxf(acc[4] * inv + bB.x, 0.f), v5 = fmaxf(acc[5] * inv + bB.y, 0.f);
    float v6 = fmaxf(acc[6] * inv + bB.z, 0.f), v7 = fmaxf(acc[7] * inv + bB.w, 0.f);
    __half2 o0 = __floats2half2_rn(v0, v1);
    __half2 o1 = __floats2half2_rn(v2, v3);
    __half2 o2 = __floats2half2_rn(v4, v5);
    __half2 o3 = __floats2half2_rn(v6, v7);
    uint4 ov = make_uint4(*(uint32_t*)&o0, *(uint32_t*)&o1, *(uint32_t*)&o2, *(uint32_t*)&o3);
    *(uint4*)(g_ah + (size_t)dst * HC + c8) = ov;
}

// ---------------- layer-2 aggregation: out[dst,c] = relu(mean_h(inv_h*sum ex*hh) + b2) ----------------
__global__ __launch_bounds__(128)
void k_agg2(const float* __restrict__ b2, float* __restrict__ out)
{
    __shared__ float s0[64], s1[64];
    int dst = blockIdx.x;
    int t   = threadIdx.x;          // 0..127
    int grp = t >> 6;               // 0..1: heads [grp*10, grp*10+10)
    int c2  = (t & 63) * 2;         // col pair
    int h0  = grp * 10;
    int p0 = g_rowptr[dst], p1 = g_rowptr[dst + 1];
    float invs[10];
    #pragma unroll
    for (int j = 0; j < 10; j++) invs[j] = __ldg(&g_inv[dst * H + h0 + j]);

    float a0 = 0.f, a1 = 0.f;
    int p = p0;
    for (; p + 2 <= p1; p += 2) {
        const __half* hs0 = g_hh + (size_t)__ldg(&g_csrc[p]) * HC;
        const __half* hs1 = g_hh + (size_t)__ldg(&g_csrc[p + 1]) * HC;
        const float*  ap0 = &g_alpha[(size_t)p * H + h0];
        const float*  ap1 = &g_alpha[(size_t)(p + 1) * H + h0];
        #pragma unroll
        for (int j = 0; j < 10; j++) {
            float al0 = __ldg(&ap0[j]) * invs[j];
            float al1 = __ldg(&ap1[j]) * invs[j];
            float2 f0 = __half22float2(*(const __half2*)&hs0[(h0 + j) * C + c2]);
            float2 f1 = __half22float2(*(const __half2*)&hs1[(h0 + j) * C + c2]);
            a0 += al0 * f0.x + al1 * f1.x;
            a1 += al0 * f0.y + al1 * f1.y;
        }
    }
    if (p < p1) {
        const __half* hs = g_hh + (size_t)__ldg(&g_csrc[p]) * HC;
        const float*  ap = &g_alpha[(size_t)p * H + h0];
        #pragma unroll
        for (int j = 0; j < 10; j++) {
            float al = __ldg(&ap[j]) * invs[j];
            float2 f = __half22float2(*(const __half2*)&hs[(h0 + j) * C + c2]);
            a0 += al * f.x;
            a1 += al * f.y;
        }
    }
    if (grp == 1) { s0[t & 63] = a0; s1[t & 63] = a1; }
    __syncthreads();
    if (grp == 0) {
        float v0 = (a0 + s0[t]) * (1.f / (float)H) + b2[c2];
        float v1 = (a1 + s1[t]) * (1.f / (float)H) + b2[c2 + 1];
        *(float2*)&out[dst * C + c2] = make_float2(fmaxf(v0, 0.f), fmaxf(v1, 0.f));
    }
}

// ---------------- launch ----------------
extern "C" void kernel_launch(void* const* d_in, const int* in_sizes, int n_in,
                              void* d_out, int out_size)
{
    const float* x   = (const float*)d_in[0];
    const int*   ei  = (const int*)d_in[1];
    const float* W1  = (const float*)d_in[2];
    const float* as1 = (const float*)d_in[3];
    const float* ad1 = (const float*)d_in[4];
    const float* b1  = (const float*)d_in[5];
    const float* W2  = (const float*)d_in[6];
    const float* as2 = (const float*)d_in[7];
    const float* ad2 = (const float*)d_in[8];
    const float* b2  = (const float*)d_in[9];
    float* out = (float*)d_out;

    cudaFuncSetAttribute(k_hgemm, cudaFuncAttributeMaxDynamicSharedMemorySize, GSMEM);

    dim3 gg(HC / 128, M_PAD / 128);                 // (20, 79)
    int sm_blocks = (N_NODES * H + 255) / 256;
    dim3 wsb(32, 8);

    // ----- layer 1 (k_hgemm at launch #4 so ncu's fixed capture hits it) -----
    int a1blocks = (N_NODES * (K1_PAD / 4) + 255) / 256;
    k_acvt<<<a1blocks, 256>>>(x, G_IN, K1_PAD);                      // 1
    k_wsplit<<<dim3(K1_PAD / 32, HC / 32), wsb>>>(W1, G_IN, K1_PAD); // 2
    k_detect<<<1, 256>>>(ei);                                        // 3
    k_hgemm<<<gg, 128, GSMEM>>>(K1_PAD, as1, ad1);                   // 4 (att fused)
    // edge normalization + CSR build
    k_norm  <<<(N_EDGES + 255) / 256, 256>>>(ei);
    k_zero_deg<<<(N_NODES + 255) / 256, 256>>>();
    k_count  <<<(EE + 255) / 256, 256>>>();
    k_scan   <<<1, 1024>>>();
    k_scatter<<<(EE + 255) / 256, 256>>>();
    // layer-1 edge phase
    k_softmax<<<sm_blocks, 256>>>();
    k_agg1<<<N_NODES, 320>>>(b1);

    // ----- layer 2 -----
    k_wsplit<<<dim3(HC / 32, HC / 32), wsb>>>(W2, HC, HC);
    k_hgemm<<<gg, 128, GSMEM>>>(HC, as2, ad2);
    k_softmax<<<sm_blocks, 256>>>();
    k_agg2<<<N_NODES, 128>>>(b2, out);
}

// round 14
// speedup vs baseline: 7.0782x; 1.0051x over previous
#include <cuda_runtime.h>
#include <cuda_fp16.h>
#include <cstdint>

// ---------------- problem constants ----------------
#define N_NODES 10000
#define M_PAD   10112            // 79 * 128
#define N_EDGES 100000
#define EE      110000           // edges + self loops
#define G_IN    2000
#define K1_PAD  2048
#define H       20
#define C       128
#define HC      2560             // H * C
#define NEG_SLOPE 0.2f

// ---------------- scratch (device globals; no allocations) ----------------
__device__ __half g_hh[(size_t)N_NODES * HC];    // fp16 GEMM output (for aggregations)
__device__ float  g_asrc[N_NODES * H];
__device__ float  g_adst[N_NODES * H];
__device__ __half g_alpha[(size_t)EE * H];       // unnormalized exp (fp16)
__device__ float  g_inv[N_NODES * H];            // 1/sum per (dst, head)
__device__ int    g_rowptr[N_NODES + 1];
__device__ int    g_deg[N_NODES];
__device__ int    g_fill[N_NODES];
__device__ int    g_csrc[EE];
__device__ int    g_is64;
__device__ int    g_esrc[N_EDGES];
__device__ int    g_edst[N_EDGES];
// fp16 GEMM operands: A [m][kpad], W^T [n][kpad]
__device__ __half g_ah[(size_t)M_PAD * HC];
__device__ __half g_wt[(size_t)HC * HC];

// ---------------- helpers ----------------
__device__ __forceinline__ uint32_t smem_u32(const void* p) {
    uint32_t a;
    asm("{ .reg .u64 t; cvta.to.shared.u64 t, %1; cvt.u32.u64 %0, t; }" : "=r"(a) : "l"(p));
    return a;
}
#define SWZ(off) ((off) ^ (((off) >> 3) & 0x70))

__device__ __forceinline__ void cp16(uint32_t dst, const void* src) {
    asm volatile("cp.async.cg.shared.global [%0], [%1], 16;" :: "r"(dst), "l"(src) : "memory");
}
__device__ __forceinline__ void cp_commit() {
    asm volatile("cp.async.commit_group;" ::: "memory");
}
template <int X> __device__ __forceinline__ void cp_wait() {
    asm volatile("cp.async.wait_group %0;" :: "n"(X) : "memory");
}
#define LDSM4(r0, r1, r2, r3, addr) \
    asm volatile("ldmatrix.sync.aligned.m8n8.x4.shared.b16 {%0,%1,%2,%3}, [%4];" \
        : "=r"(r0), "=r"(r1), "=r"(r2), "=r"(r3) : "r"(addr))
#define MMA(c, a, b) \
    asm volatile("mma.sync.aligned.m16n8k16.row.col.f32.f16.f16.f32 " \
        "{%0,%1,%2,%3}, {%4,%5,%6,%7}, {%8,%9}, {%0,%1,%2,%3};" \
        : "+f"((c)[0]), "+f"((c)[1]), "+f"((c)[2]), "+f"((c)[3]) \
        : "r"((a)[0]), "r"((a)[1]), "r"((a)[2]), "r"((a)[3]), "r"((b)[0]), "r"((b)[1]))

// ---------------- prep: zero degrees + edge dtype detection ----------------
__global__ void k_prep(const int* __restrict__ ei32) {
    int i = blockIdx.x * blockDim.x + threadIdx.x;
    if (i < N_NODES) g_deg[i] = 0;
    if (blockIdx.x == 0) {
        __shared__ int any;
        if (threadIdx.x == 0) any = 0;
        __syncthreads();
        if (ei32[2 * threadIdx.x + 1] != 0) atomicOr(&any, 1);
        __syncthreads();
        if (threadIdx.x == 0) g_is64 = (any == 0) ? 1 : 0;
    }
}
__global__ void k_norm(const int* __restrict__ ei32) {
    int e = blockIdx.x * blockDim.x + threadIdx.x;
    if (e >= N_EDGES) return;
    if (g_is64) { g_esrc[e] = ei32[2 * e]; g_edst[e] = ei32[2 * N_EDGES + 2 * e]; }
    else        { g_esrc[e] = ei32[e];     g_edst[e] = ei32[N_EDGES + e]; }
}

// ---------------- CSR build ----------------
__global__ void k_count() {
    int e = blockIdx.x * blockDim.x + threadIdx.x;
    if (e >= EE) return;
    int dst = (e < N_EDGES) ? g_edst[e] : (e - N_EDGES);
    atomicAdd(&g_deg[dst], 1);
}
__global__ void k_scan() {
    __shared__ int part[1024];
    int t = threadIdx.x;
    const int CH = (N_NODES + 1023) / 1024;
    int base = t * CH, s = 0;
    for (int i = 0; i < CH; i++) { int idx = base + i; if (idx < N_NODES) s += g_deg[idx]; }
    part[t] = s;
    __syncthreads();
    for (int o = 1; o < 1024; o <<= 1) {
        int v = (t >= o) ? part[t - o] : 0;
        __syncthreads(); part[t] += v; __syncthreads();
    }
    int run = (t > 0) ? part[t - 1] : 0;
    for (int i = 0; i < CH; i++) {
        int idx = base + i;
        if (idx < N_NODES) { g_rowptr[idx] = run; g_fill[idx] = run; run += g_deg[idx]; }
    }
    if (t == 1023) g_rowptr[N_NODES] = part[1023];
}
__global__ void k_scatter() {
    int e = blockIdx.x * blockDim.x + threadIdx.x;
    if (e >= EE) return;
    int src, dst;
    if (e < N_EDGES) { src = g_esrc[e]; dst = g_edst[e]; }
    else             { src = e - N_EDGES; dst = src; }
    int pos = atomicAdd(&g_fill[dst], 1);
    g_csrc[pos] = src;
}

// ---------------- layer-1 activation convert: g_ah[m][kpad] = fp16(x[m][k]) ----------------
__global__ void k_acvt(const float* __restrict__ A, int K, int KPAD) {
    int idx = blockIdx.x * blockDim.x + threadIdx.x;
    int rowlen4 = KPAD >> 2;
    if (idx >= N_NODES * rowlen4) return;
    int row = idx / rowlen4;
    int c4  = (idx - row * rowlen4) << 2;
    float v[4];
    #pragma unroll
    for (int j = 0; j < 4; j++) v[j] = (c4 + j < K) ? A[(size_t)row * K + c4 + j] : 0.f;
    uint32_t w0 = (uint32_t)__half_as_ushort(__float2half_rn(v[0]))
                | ((uint32_t)__half_as_ushort(__float2half_rn(v[1])) << 16);
    uint32_t w1 = (uint32_t)__half_as_ushort(__float2half_rn(v[2]))
                | ((uint32_t)__half_as_ushort(__float2half_rn(v[3])) << 16);
    *(uint2*)&g_ah[(size_t)row * KPAD + c4] = make_uint2(w0, w1);
}

// ---------------- W transpose to fp16: g_wt[n][kpad] = fp16(W[k][n]) ----------------
__global__ void k_wsplit(const float* __restrict__ W, int K, int KPAD) {
    __shared__ float tile[32][33];
    int n0 = blockIdx.y * 32, k0 = blockIdx.x * 32;
    int tx = threadIdx.x, ty = threadIdx.y;     // (32, 8)
    #pragma unroll
    for (int s = 0; s < 32; s += 8) {
        int k = k0 + ty + s;
        tile[ty + s][tx] = (k < K) ? W[(size_t)k * HC + n0 + tx] : 0.f;
    }
    __syncthreads();
    #pragma unroll
    for (int s = 0; s < 32; s += 8) {
        int n = n0 + ty + s;
        int k = k0 + tx;
        g_wt[(size_t)n * KPAD + k] = __float2half_rn(tile[tx][ty + s]);
    }
}

// ---------------- fp16 HMMA GEMM + fused attention scores ----------------
// CTA tile 128x128 (= 1 head), 4 warps (128 thr), warp tile 64x64,
// K staged 64, 3-stage cp.async pipeline, 2 CTAs/SM.
#define STG3   32768              // A 16K | B 16K
#define OFF_B  16384
#define GSMEM  (3 * STG3)         // 96 KB

__global__ __launch_bounds__(128, 2)
void k_hgemm(int kpad, const float* __restrict__ wsrc, const float* __restrict__ wdst)
{
    extern __shared__ char smem[];
    uint32_t sb = smem_u32(smem);
    int tid  = threadIdx.x;
    int lane = tid & 31;
    int wid  = tid >> 5;            // 0..3
    int wr   = wid >> 1;            // 0..1  (64-row slabs)
    int wc   = wid & 1;             // 0..1  (64-col slabs)
    int row0 = blockIdx.y * 128;
    int col0 = blockIdx.x * 128;
    int nkb  = kpad >> 6;

    float acc[4][8][4];
    #pragma unroll
    for (int i = 0; i < 4; i++)
        #pragma unroll
        for (int j = 0; j < 8; j++)
            #pragma unroll
            for (int q = 0; q < 4; q++) acc[i][j][q] = 0.f;

    // ---- stage issue: 16 cp.async per thread (32 KB) ----
    auto issue = [&](int kb) {
        int kt = kb << 6;
        uint32_t st = sb + (kb % 3) * STG3;
        #pragma unroll
        for (int i = 0; i < 8; i++) {                 // A: 128 rows
            int idx = i * 128 + tid;
            int r = idx >> 3, c = idx & 7;
            uint32_t off = SWZ((uint32_t)(r * 128 + c * 16));
            cp16(st + off, g_ah + (size_t)(row0 + r) * kpad + kt + c * 8);
        }
        #pragma unroll
        for (int i = 0; i < 8; i++) {                 // B: 128 rows
            int idx = i * 128 + tid;
            int r = idx >> 3, c = idx & 7;
            uint32_t off = SWZ((uint32_t)(r * 128 + c * 16));
            cp16(st + OFF_B + off, g_wt + (size_t)(col0 + r) * kpad + kt + c * 8);
        }
    };

    issue(0); cp_commit();
    if (nkb > 1) issue(1);
    cp_commit();

    for (int kb = 0; kb < nkb; kb++) {
        cp_wait<1>();
        __syncthreads();
        if (kb + 2 < nkb) issue(kb + 2);
        cp_commit();

        uint32_t tb = sb + (kb % 3) * STG3;
        #pragma unroll
        for (int k16 = 0; k16 < 4; k16++) {
            uint32_t ah[4][4];
            int arow = wr * 64 + (lane & 15);
            uint32_t acol = (uint32_t)(k16 * 32 + (lane >> 4) * 16);
            #pragma unroll
            for (int mt = 0; mt < 4; mt++) {
                uint32_t off = SWZ((uint32_t)((arow + mt * 16) * 128) + acol);
                LDSM4(ah[mt][0], ah[mt][1], ah[mt][2], ah[mt][3], tb + off);
            }
            int mi = lane >> 3;
            int brow = wc * 64 + ((mi >> 1) << 3) + (lane & 7);
            uint32_t bcol = (uint32_t)(k16 * 32 + (mi & 1) * 16);
            #pragma unroll
            for (int half = 0; half < 2; half++) {
                uint32_t bh[4][2];
                #pragma unroll
                for (int q = 0; q < 2; q++) {
                    int nt2 = half * 2 + q;
                    uint32_t off = SWZ((uint32_t)((brow + nt2 * 16) * 128) + bcol);
                    LDSM4(bh[q * 2][0], bh[q * 2][1], bh[q * 2 + 1][0], bh[q * 2 + 1][1],
                          tb + OFF_B + off);
                }
                #pragma unroll
                for (int mt = 0; mt < 4; mt++)
                    #pragma unroll
                    for (int ntl = 0; ntl < 4; ntl++)
                        MMA(acc[mt][half * 4 + ntl], ah[mt], bh[ntl]);
            }
        }
    }

    // ---- epilogue 1: fp16 feature store ----
    #pragma unroll
    for (int mt = 0; mt < 4; mt++) {
        int gr = row0 + wr * 64 + mt * 16 + (lane >> 2);
        #pragma unroll
        for (int nt = 0; nt < 8; nt++) {
            int gc = col0 + wc * 64 + nt * 8 + (lane & 3) * 2;
            if (gr < N_NODES)
                *(__half2*)&g_hh[(size_t)gr * HC + gc] =
                    __floats2half2_rn(acc[mt][nt][0], acc[mt][nt][1]);
            if (gr + 8 < N_NODES)
                *(__half2*)&g_hh[(size_t)(gr + 8) * HC + gc] =
                    __floats2half2_rn(acc[mt][nt][2], acc[mt][nt][3]);
        }
    }

    // ---- epilogue 2: fused attention scores (CTA = head blockIdx.x) ----
    __syncthreads();                      // stage smem no longer needed
    float* s_red = (float*)smem;          // [128 rows][2 contrib][2 src/dst]
    int hdg = blockIdx.x;
    float wS0[8], wS1[8], wD0[8], wD1[8];
    #pragma unroll
    for (int nt = 0; nt < 8; nt++) {
        int cloc = wc * 64 + nt * 8 + (lane & 3) * 2;
        wS0[nt] = __ldg(&wsrc[hdg * C + cloc]);
        wS1[nt] = __ldg(&wsrc[hdg * C + cloc + 1]);
        wD0[nt] = __ldg(&wdst[hdg * C + cloc]);
        wD1[nt] = __ldg(&wdst[hdg * C + cloc + 1]);
    }
    #pragma unroll
    for (int mt = 0; mt < 4; mt++) {
        float sa = 0.f, sbv = 0.f, da = 0.f, db = 0.f;
        #pragma unroll
        for (int nt = 0; nt < 8; nt++) {
            sa  += acc[mt][nt][0] * wS0[nt] + acc[mt][nt][1] * wS1[nt];
            sbv += acc[mt][nt][2] * wS0[nt] + acc[mt][nt][3] * wS1[nt];
            da  += acc[mt][nt][0] * wD0[nt] + acc[mt][nt][1] * wD1[nt];
            db  += acc[mt][nt][2] * wD0[nt] + acc[mt][nt][3] * wD1[nt];
        }
        #pragma unroll
        for (int o = 1; o <= 2; o <<= 1) {
            sa  += __shfl_xor_sync(0xffffffffu, sa,  o);
            sbv += __shfl_xor_sync(0xffffffffu, sbv, o);
            da  += __shfl_xor_sync(0xffffffffu, da,  o);
            db  += __shfl_xor_sync(0xffffffffu, db,  o);
        }
        if ((lane & 3) == 0) {
            int rA = wr * 64 + mt * 16 + (lane >> 2);
            int rB = rA + 8;
            s_red[(rA * 2 + wc) * 2 + 0] = sa;
            s_red[(rA * 2 + wc) * 2 + 1] = da;
            s_red[(rB * 2 + wc) * 2 + 0] = sbv;
            s_red[(rB * 2 + wc) * 2 + 1] = db;
        }
    }
    __syncthreads();
    {
        int gr = row0 + tid;
        if (gr < N_NODES) {
            float vs = s_red[(tid * 2 + 0) * 2 + 0] + s_red[(tid * 2 + 1) * 2 + 0];
            float vd = s_red[(tid * 2 + 0) * 2 + 1] + s_red[(tid * 2 + 1) * 2 + 1];
            g_asrc[gr * H + hdg] = vs;
            g_adst[gr * H + hdg] = vd;
        }
    }
}

// ---------------- per-(dst,head) softmax: unnormalized exp (fp16) + 1/sum ----------------
__global__ void k_softmax() {
    int idx = blockIdx.x * blockDim.x + threadIdx.x;
    if (idx >= N_NODES * H) return;
    int dst = idx / H;
    int hh  = idx - dst * H;
    float ad = g_adst[dst * H + hh];
    int p0 = g_rowptr[dst], p1 = g_rowptr[dst + 1];
    float m = -1e30f;
    for (int p = p0; p < p1; p++) {
        int s = g_csrc[p];
        float ev = g_asrc[s * H + hh] + ad;
        ev = (ev > 0.f) ? ev : NEG_SLOPE * ev;
        g_alpha[(size_t)p * H + hh] = __float2half_rn(ev);
        m = fmaxf(m, ev);
    }
    float sum = 0.f;
    for (int p = p0; p < p1; p++) {
        float ex = __expf(__half2float(g_alpha[(size_t)p * H + hh]) - m);
        g_alpha[(size_t)p * H + hh] = __float2half_rn(ex);
        sum += ex;
    }
    g_inv[dst * H + hh] = 1.f / sum;
}

// ---------------- layer-1 aggregation: g_ah[dst,:] = fp16(relu(inv*sum ex*hh + b1)) ----------------
__global__ __launch_bounds__(320)
void k_agg1(const float* __restrict__ b1)
{
    int dst = blockIdx.x;
    int t   = threadIdx.x;          // 0..319
    int c8  = t * 8;                // 8 cols per thread (within head t>>4)
    int hh  = t >> 4;
    int p0 = g_rowptr[dst], p1 = g_rowptr[dst + 1];
    float inv = __ldg(&g_inv[dst * H + hh]);
    float acc[8];
    #pragma unroll
    for (int j = 0; j < 8; j++) acc[j] = 0.f;

    int p = p0;
    for (; p + 4 <= p1; p += 4) {
        float al[4];
        uint4 v[4];
        #pragma unroll
        for (int e = 0; e < 4; e++) {
            al[e] = __half2float(__ldg(&g_alpha[(size_t)(p + e) * H + hh]));
            v[e]  = *(const uint4*)(g_hh + (size_t)__ldg(&g_csrc[p + e]) * HC + c8);
        }
        #pragma unroll
        for (int e = 0; e < 4; e++) {
            float2 f0 = __half22float2(*(__half2*)&v[e].x);
            float2 f1 = __half22float2(*(__half2*)&v[e].y);
            float2 f2 = __half22float2(*(__half2*)&v[e].z);
            float2 f3 = __half22float2(*(__half2*)&v[e].w);
            acc[0] += al[e] * f0.x; acc[1] += al[e] * f0.y;
            acc[2] += al[e] * f1.x; acc[3] += al[e] * f1.y;
            acc[4] += al[e] * f2.x; acc[5] += al[e] * f2.y;
            acc[6] += al[e] * f3.x; acc[7] += al[e] * f3.y;
        }
    }
    for (; p < p1; p++) {
        float al = __half2float(__ldg(&g_alpha[(size_t)p * H + hh]));
        uint4 v = *(const uint4*)(g_hh + (size_t)__ldg(&g_csrc[p]) * HC + c8);
        float2 f0 = __half22float2(*(__half2*)&v.x), f1 = __half22float2(*(__half2*)&v.y);
        float2 f2 = __half22float2(*(__half2*)&v.z), f3 = __half22float2(*(__half2*)&v.w);
        acc[0] += al * f0.x; acc[1] += al * f0.y;
        acc[2] += al * f1.x; acc[3] += al * f1.y;
        acc[4] += al * f2.x; acc[5] += al * f2.y;
        acc[6] += al * f3.x; acc[7] += al * f3.y;
    }
    float4 bA = *(const float4*)&b1[c8];
    float4 bB = *(const float4*)&b1[c8 + 4];
    float v0 = fmaxf(acc[0] * inv + bA.x, 0.f), v1 = fmaxf(acc[1] * inv + bA.y, 0.f);
    float v2 = fmaxf(acc[2] * inv + bA.z, 0.f), v3 = fmaxf(acc[3] * inv + bA.w, 0.f);
    float v4 = fmaxf(acc[4] * inv + bB.x, 0.f), v5 = fmaxf(acc[5] * inv + bB.y, 0.f);
    float v6 = fmaxf(acc[6] * inv + bB.z, 0.f), v7 = fmaxf(acc[7] * inv + bB.w, 0.f);
    __half2 o0 = __floats2half2_rn(v0, v1);
    __half2 o1 = __floats2half2_rn(v2, v3);
    __half2 o2 = __floats2half2_rn(v4, v5);
    __half2 o3 = __floats2half2_rn(v6, v7);
    uint4 ov = make_uint4(*(uint32_t*)&o0, *(uint32_t*)&o1, *(uint32_t*)&o2, *(uint32_t*)&o3);
    *(uint4*)(g_ah + (size_t)dst * HC + c8) = ov;
}

// ---------------- layer-2 aggregation: out[dst,c] = relu(mean_h(inv_h*sum ex*hh) + b2) ----------------
__global__ __launch_bounds__(128)
void k_agg2(const float* __restrict__ b2, float* __restrict__ out)
{
    __shared__ float s0[64], s1[64];
    int dst = blockIdx.x;
    int t   = threadIdx.x;          // 0..127
    int grp = t >> 6;               // 0..1: heads [grp*10, grp*10+10)
    int c2  = (t & 63) * 2;         // col pair
    int h0  = grp * 10;
    int p0 = g_rowptr[dst], p1 = g_rowptr[dst + 1];
    float invs[10];
    #pragma unroll
    for (int j = 0; j < 10; j++) invs[j] = __ldg(&g_inv[dst * H + h0 + j]);

    float a0 = 0.f, a1 = 0.f;
    int p = p0;
    for (; p + 2 <= p1; p += 2) {
        const __half* hs0 = g_hh + (size_t)__ldg(&g_csrc[p]) * HC;
        const __half* hs1 = g_hh + (size_t)__ldg(&g_csrc[p + 1]) * HC;
        const __half*  ap0 = &g_alpha[(size_t)p * H + h0];
        const __half*  ap1 = &g_alpha[(size_t)(p + 1) * H + h0];
        #pragma unroll
        for (int j = 0; j < 10; j++) {
            float al0 = __half2float(__ldg(&ap0[j])) * invs[j];
            float al1 = __half2float(__ldg(&ap1[j])) * invs[j];
            float2 f0 = __half22float2(*(const __half2*)&hs0[(h0 + j) * C + c2]);
            float2 f1 = __half22float2(*(const __half2*)&hs1[(h0 + j) * C + c2]);
            a0 += al0 * f0.x + al1 * f1.x;
            a1 += al0 * f0.y + al1 * f1.y;
        }
    }
    if (p < p1) {
        const __half* hs = g_hh + (size_t)__ldg(&g_csrc[p]) * HC;
        const __half*  ap = &g_alpha[(size_t)p * H + h0];
        #pragma unroll
        for (int j = 0; j < 10; j++) {
            float al = __half2float(__ldg(&ap[j])) * invs[j];
            float2 f = __half22float2(*(const __half2*)&hs[(h0 + j) * C + c2]);
            a0 += al * f.x;
            a1 += al * f.y;
        }
    }
    if (grp == 1) { s0[t & 63] = a0; s1[t & 63] = a1; }
    __syncthreads();
    if (grp == 0) {
        float v0 = (a0 + s0[t]) * (1.f / (float)H) + b2[c2];
        float v1 = (a1 + s1[t]) * (1.f / (float)H) + b2[c2 + 1];
        *(float2*)&out[dst * C + c2] = make_float2(fmaxf(v0, 0.f), fmaxf(v1, 0.f));
    }
}

// ---------------- launch ----------------
extern "C" void kernel_launch(void* const* d_in, const int* in_sizes, int n_in,
                              void* d_out, int out_size)
{
    const float* x   = (const float*)d_in[0];
    const int*   ei  = (const int*)d_in[1];
    const float* W1  = (const float*)d_in[2];
    const float* as1 = (const float*)d_in[3];
    const float* ad1 = (const float*)d_in[4];
    const float* b1  = (const float*)d_in[5];
    const float* W2  = (const float*)d_in[6];
    const float* as2 = (const float*)d_in[7];
    const float* ad2 = (const float*)d_in[8];
    const float* b2  = (const float*)d_in[9];
    float* out = (float*)d_out;

    cudaFuncSetAttribute(k_hgemm, cudaFuncAttributeMaxDynamicSharedMemorySize, GSMEM);

    dim3 gg(HC / 128, M_PAD / 128);                 // (20, 79)
    int sm_blocks = (N_NODES * H + 255) / 256;
    dim3 wsb(32, 8);

    // ----- layer 1 (k_hgemm at launch #4 so ncu's fixed capture hits it) -----
    int a1blocks = (N_NODES * (K1_PAD / 4) + 255) / 256;
    k_acvt<<<a1blocks, 256>>>(x, G_IN, K1_PAD);                      // 1
    k_wsplit<<<dim3(K1_PAD / 32, HC / 32), wsb>>>(W1, G_IN, K1_PAD); // 2
    k_prep<<<(N_NODES + 255) / 256, 256>>>(ei);                      // 3
    k_hgemm<<<gg, 128, GSMEM>>>(K1_PAD, as1, ad1);                   // 4 (att fused)
    // edge normalization + CSR build
    k_norm  <<<(N_EDGES + 255) / 256, 256>>>(ei);
    k_count <<<(EE + 255) / 256, 256>>>();
    k_scan  <<<1, 1024>>>();
    k_scatter<<<(EE + 255) / 256, 256>>>();
    // layer-1 edge phase
    k_softmax<<<sm_blocks, 256>>>();
    k_agg1<<<N_NODES, 320>>>(b1);

    // ----- layer 2 -----
    k_wsplit<<<dim3(HC / 32, HC / 32), wsb>>>(W2, HC, HC);
    k_hgemm<<<gg, 128, GSMEM>>>(HC, as2, ad2);
    k_softmax<<<sm_blocks, 256>>>();
    k_agg2<<<N_NODES, 128>>>(b2, out);
}